// round 12
// baseline (speedup 1.0000x reference)
#include <cuda_runtime.h>
#include <cuda_bf16.h>
#include <mma.h>
#include <math.h>
#include <cstdint>

using namespace nvcuda;

#define NN 4096
#define FF 128
#define HH 128
#define KK 4
#define CC 10
#define H4 512
#define MAXNB 256

typedef __nv_bfloat16 bf16;

// ---------------- scratch ----------------
__device__ float g_dinv[NN * KK];
__device__ int   g_cnt[NN * KK];
__device__ int   g_cols[(size_t)NN * KK * MAXNB];
__device__ float g_T[(size_t)KK * NN * HH];
__device__ float g_h1f[(size_t)KK * NN * HH];
__device__ float g_ww[(size_t)KK * HH * HH];
__device__ float g_bw[KK * HH];
__device__ float g_gnn[(size_t)NN * KK * HH];
__device__ float g_XG[(size_t)2 * NN * KK * H4];
__device__ float g_cbuf[(size_t)2 * NN * HH];
__device__ float g_hfwd[(size_t)NN * KK * HH];
__device__ float g_hbwd[(size_t)NN * KK * HH];

// pre-split bf16 hi/lo buffers
__device__ bf16 g_feat_hi[NN * FF],            g_feat_lo[NN * FF];
__device__ bf16 g_w1_hi[KK * FF * HH],         g_w1_lo[KK * FF * HH];
__device__ bf16 g_w2_hi[KK * HH * HH],         g_w2_lo[KK * HH * HH];
__device__ bf16 g_ww_hi[KK * HH * HH],         g_ww_lo[KK * HH * HH];
__device__ bf16 g_wihf_hi[H4 * HH],            g_wihf_lo[H4 * HH];
__device__ bf16 g_whhf_hi[H4 * HH],            g_whhf_lo[H4 * HH];
__device__ bf16 g_wihb_hi[H4 * HH],            g_wihb_lo[H4 * HH];
__device__ bf16 g_whhb_hi[H4 * HH],            g_whhb_lo[H4 * HH];
__device__ bf16 g_gnn_hi[(size_t)NN * KK * HH],g_gnn_lo[(size_t)NN * KK * HH];
__device__ bf16 g_hb_hi[(size_t)2 * NN * HH],  g_hb_lo[(size_t)2 * NN * HH];

__device__ __forceinline__ uint32_t smem_u32(const void* p) {
    uint32_t a;
    asm("{ .reg .u64 t; cvta.to.shared.u64 t, %1; cvt.u32.u64 %0, t; }" : "=r"(a) : "l"(p));
    return a;
}

__device__ __forceinline__ void split1(float x, bf16* hi, bf16* lo, size_t idx) {
    bf16 h = __float2bfloat16(x);
    hi[idx] = h;
    lo[idx] = __float2bfloat16(x - __bfloat162float(h));
}

// ============================================================================
// wmma bf16 split-precision GEMM: 128x64 tiles (x NCH chunks of N per block,
// A staged once), 256 thr, cp.async staging, 2 blocks/SM.
// ============================================================================
#define LDA 136
#define A_E (128 * LDA)
#define B_E 9216
#define SMEM_BYTES ((2 * A_E + 2 * B_E) * 2)

template <int BCOL, int NCH>
__global__ __launch_bounds__(256, 2)
void wmma_gemm(const bf16* __restrict__ Ahi_g, const bf16* __restrict__ Alo_g,
               long a_zrows,
               const bf16* __restrict__ Bhi0, const bf16* __restrict__ Blo0,
               const bf16* __restrict__ Bhi1, const bf16* __restrict__ Blo1,
               long b_zstride, int ldb,
               float* __restrict__ C, long c_zstride, int ldc) {
    extern __shared__ bf16 sm[];
    bf16* Ahi = sm;
    bf16* Alo = sm + A_E;
    bf16* Bhi = sm + 2 * A_E;
    bf16* Blo = sm + 2 * A_E + B_E;

    int tid = threadIdx.x;
    int z = blockIdx.z;
    long arow0 = (long)blockIdx.y * 128 + (long)z * a_zrows;
    const bf16* bhp = (Bhi1 && z) ? Bhi1 : (Bhi0 + (size_t)z * b_zstride);
    const bf16* blp = (Blo1 && z) ? Blo1 : (Blo0 + (size_t)z * b_zstride);

    uint32_t sb = smem_u32(sm);
    const bf16* asrc0 = Ahi_g + arow0 * 128;
    const bf16* asrc1 = Alo_g + arow0 * 128;
#pragma unroll
    for (int t = 0; t < 2; t++) {
        const bf16* gb = t ? asrc1 : asrc0;
        uint32_t base = sb + t * (A_E * 2);
#pragma unroll
        for (int it = 0; it < 8; it++) {
            int i = it * 256 + tid;
            int r = i >> 4, ck = i & 15;
            const char* g = (const char*)(gb + (size_t)r * 128) + ck * 16;
            uint32_t s = base + r * 272 + ck * 16;
            asm volatile("cp.async.cg.shared.global [%0], [%1], 16;" :: "r"(s), "l"(g));
        }
    }

    int w = tid >> 5;
    int wm = (w & 3) * 32;
    int wn = (w >> 2) * 32;

    for (int ch = 0; ch < NCH; ch++) {
        int bn = (blockIdx.x * NCH + ch) * 64;
        // ---- stage B chunk ----
        if (!BCOL) {
#pragma unroll
            for (int t = 0; t < 2; t++) {
                const bf16* gb = (t ? blp : bhp) + bn;
                uint32_t base = sb + (2 * A_E + t * B_E) * 2;
#pragma unroll
                for (int it = 0; it < 4; it++) {
                    int i = it * 256 + tid;
                    int r = i >> 3, ck = i & 7;
                    const char* g = (const char*)(gb + (size_t)r * ldb) + ck * 16;
                    uint32_t s = base + r * 144 + ck * 16;
                    asm volatile("cp.async.cg.shared.global [%0], [%1], 16;" :: "r"(s), "l"(g));
                }
            }
        } else {
#pragma unroll
            for (int t = 0; t < 2; t++) {
                const bf16* gb = (t ? blp : bhp) + (size_t)bn * 128;
                uint32_t base = sb + (2 * A_E + t * B_E) * 2;
#pragma unroll
                for (int it = 0; it < 4; it++) {
                    int i = it * 256 + tid;
                    int r = i >> 4, ck = i & 15;
                    const char* g = (const char*)(gb + (size_t)r * 128) + ck * 16;
                    uint32_t s = base + r * 272 + ck * 16;
                    asm volatile("cp.async.cg.shared.global [%0], [%1], 16;" :: "r"(s), "l"(g));
                }
            }
        }
        asm volatile("cp.async.commit_group;");
        asm volatile("cp.async.wait_group 0;");
        __syncthreads();

        wmma::fragment<wmma::accumulator, 16, 16, 16, float> acc[2][2];
#pragma unroll
        for (int i = 0; i < 2; i++)
#pragma unroll
            for (int j = 0; j < 2; j++)
                wmma::fill_fragment(acc[i][j], 0.0f);

#pragma unroll
        for (int kk = 0; kk < 128; kk += 16) {
            wmma::fragment<wmma::matrix_a, 16, 16, 16, bf16, wmma::row_major> ah[2], al[2];
#pragma unroll
            for (int i = 0; i < 2; i++) {
                wmma::load_matrix_sync(ah[i], &Ahi[(wm + 16 * i) * LDA + kk], LDA);
                wmma::load_matrix_sync(al[i], &Alo[(wm + 16 * i) * LDA + kk], LDA);
            }
            if (!BCOL) {
                wmma::fragment<wmma::matrix_b, 16, 16, 16, bf16, wmma::row_major> bh[2], bl[2];
#pragma unroll
                for (int j = 0; j < 2; j++) {
                    wmma::load_matrix_sync(bh[j], &Bhi[kk * 72 + wn + 16 * j], 72);
                    wmma::load_matrix_sync(bl[j], &Blo[kk * 72 + wn + 16 * j], 72);
                }
#pragma unroll
                for (int i = 0; i < 2; i++)
#pragma unroll
                    for (int j = 0; j < 2; j++) {
                        wmma::mma_sync(acc[i][j], ah[i], bh[j], acc[i][j]);
                        wmma::mma_sync(acc[i][j], ah[i], bl[j], acc[i][j]);
                        wmma::mma_sync(acc[i][j], al[i], bh[j], acc[i][j]);
                    }
            } else {
                wmma::fragment<wmma::matrix_b, 16, 16, 16, bf16, wmma::col_major> bh[2], bl[2];
#pragma unroll
                for (int j = 0; j < 2; j++) {
                    wmma::load_matrix_sync(bh[j], &Bhi[(wn + 16 * j) * 136 + kk], 136);
                    wmma::load_matrix_sync(bl[j], &Blo[(wn + 16 * j) * 136 + kk], 136);
                }
#pragma unroll
                for (int i = 0; i < 2; i++)
#pragma unroll
                    for (int j = 0; j < 2; j++) {
                        wmma::mma_sync(acc[i][j], ah[i], bh[j], acc[i][j]);
                        wmma::mma_sync(acc[i][j], ah[i], bl[j], acc[i][j]);
                        wmma::mma_sync(acc[i][j], al[i], bh[j], acc[i][j]);
                    }
            }
        }

        float* Cp = C + (size_t)z * c_zstride + ((size_t)blockIdx.y * 128) * ldc + bn;
#pragma unroll
        for (int i = 0; i < 2; i++)
#pragma unroll
            for (int j = 0; j < 2; j++)
                wmma::store_matrix_sync(&Cp[(size_t)(wm + 16 * i) * ldc + wn + 16 * j],
                                        acc[i][j], ldc, wmma::mem_row_major);
        if (ch + 1 < NCH) __syncthreads();
    }
}

// ============================================================================
// FUSED LSTM step (steps 1..3): recurrent GEMM (h @ Whh^T, split bf16, 3-pass)
// + gate math, all on-chip. Block = 64 rows x one dir; loops 4 gate chunks
// (order i, g, f, o) with ONE smem state buffer.
// smem: A(hi,lo) 2x17408B | B(hi,lo) 2x34816B | GB 64x132 f32 | SB 64x128 f32
// ============================================================================
#define F_AOFF 0
#define F_BOFF 34816
#define F_GBOFF 104448
#define F_SBOFF 138240
#define FUSED_SMEM 171008

__global__ __launch_bounds__(256, 1)
void lstm_fused_kernel(const float* __restrict__ XG,
                       const float* __restrict__ bi_f, const float* __restrict__ bh_f,
                       const float* __restrict__ bi_b, const float* __restrict__ bh_b,
                       float* __restrict__ cbuf,
                       float* __restrict__ hf, float* __restrict__ hb, int step) {
    extern __shared__ char smf[];
    bf16* Ahi = (bf16*)(smf + F_AOFF);
    bf16* Alo = (bf16*)(smf + F_AOFF + 17408);
    bf16* Bhi = (bf16*)(smf + F_BOFF);
    bf16* Blo = (bf16*)(smf + F_BOFF + 34816);
    float* GB = (float*)(smf + F_GBOFF);   // ld 132
    float* SB = (float*)(smf + F_SBOFF);   // ld 128

    int tid = threadIdx.x;
    int dir = blockIdx.y;
    int n0 = blockIdx.x * 64;
    int t = dir ? (KK - 1 - step) : step;
    const bf16* whh_hi = dir ? g_whhb_hi : g_whhf_hi;
    const bf16* whh_lo = dir ? g_whhb_lo : g_whhf_lo;
    const float* bi = dir ? bi_b : bi_f;
    const float* bh = dir ? bh_b : bh_f;
    uint32_t sb = smem_u32(smf);

    // ---- stage A (current h state, 64 rows) ----
    {
        const bf16* ah = g_hb_hi + (size_t)dir * NN * HH + (size_t)n0 * HH;
        const bf16* al = g_hb_lo + (size_t)dir * NN * HH + (size_t)n0 * HH;
#pragma unroll
        for (int b = 0; b < 2; b++) {
            const bf16* gb = b ? al : ah;
            uint32_t base = sb + F_AOFF + b * 17408;
#pragma unroll
            for (int it = 0; it < 4; it++) {
                int i = it * 256 + tid;   // 0..1023
                int r = i >> 4, ck = i & 15;
                const char* g = (const char*)(gb + (size_t)r * 128) + ck * 16;
                asm volatile("cp.async.cg.shared.global [%0], [%1], 16;"
                             :: "r"(base + r * 272 + ck * 16), "l"(g));
            }
        }
    }
    // ---- prefetch B for first gate chunk (gate 0 = input gate) ----
#pragma unroll
    for (int b = 0; b < 2; b++) {
        const bf16* gb = (b ? whh_lo : whh_hi);   // gate 0 rows start at 0
        uint32_t base = sb + F_BOFF + b * 34816;
#pragma unroll
        for (int it = 0; it < 8; it++) {
            int i = it * 256 + tid;   // 0..2047
            int r = i >> 4, ck = i & 15;
            const char* g = (const char*)(gb + (size_t)r * 128) + ck * 16;
            asm volatile("cp.async.cg.shared.global [%0], [%1], 16;"
                         :: "r"(base + r * 272 + ck * 16), "l"(g));
        }
    }
    asm volatile("cp.async.commit_group;");
    asm volatile("cp.async.wait_group 0;");
    __syncthreads();

    int w = tid >> 5;
    int wm = (w & 1) * 32;     // 2 row groups x 32 = 64 rows
    int wn = (w >> 1) * 32;    // 4 col groups x 32 = 128 cols

    const int ord[4] = {0, 2, 1, 3};   // i, g, f, o
#pragma unroll
    for (int pi = 0; pi < 4; pi++) {
        int gate = ord[pi];
        // ---- MMA: 64x128 = Ahb[64x128] @ Bchunk^T, 3-pass split ----
        wmma::fragment<wmma::accumulator, 16, 16, 16, float> acc[2][2];
#pragma unroll
        for (int i = 0; i < 2; i++)
#pragma unroll
            for (int j = 0; j < 2; j++)
                wmma::fill_fragment(acc[i][j], 0.0f);
#pragma unroll
        for (int kk = 0; kk < 128; kk += 16) {
            wmma::fragment<wmma::matrix_a, 16, 16, 16, bf16, wmma::row_major> ah[2], al[2];
#pragma unroll
            for (int i = 0; i < 2; i++) {
                wmma::load_matrix_sync(ah[i], &Ahi[(wm + 16 * i) * 136 + kk], 136);
                wmma::load_matrix_sync(al[i], &Alo[(wm + 16 * i) * 136 + kk], 136);
            }
            wmma::fragment<wmma::matrix_b, 16, 16, 16, bf16, wmma::col_major> bhf[2], blf[2];
#pragma unroll
            for (int j = 0; j < 2; j++) {
                wmma::load_matrix_sync(bhf[j], &Bhi[(wn + 16 * j) * 136 + kk], 136);
                wmma::load_matrix_sync(blf[j], &Blo[(wn + 16 * j) * 136 + kk], 136);
            }
#pragma unroll
            for (int i = 0; i < 2; i++)
#pragma unroll
                for (int j = 0; j < 2; j++) {
                    wmma::mma_sync(acc[i][j], ah[i], bhf[j], acc[i][j]);
                    wmma::mma_sync(acc[i][j], ah[i], blf[j], acc[i][j]);
                    wmma::mma_sync(acc[i][j], al[i], bhf[j], acc[i][j]);
                }
        }
        __syncthreads();   // all warps done reading B
        // ---- prefetch next gate's B during combine ----
        if (pi < 3) {
            int ng = ord[pi + 1];
#pragma unroll
            for (int b = 0; b < 2; b++) {
                const bf16* gb = (b ? whh_lo : whh_hi) + (size_t)ng * 128 * 128;
                uint32_t base = sb + F_BOFF + b * 34816;
#pragma unroll
                for (int it = 0; it < 8; it++) {
                    int i = it * 256 + tid;
                    int r = i >> 4, ck = i & 15;
                    const char* g = (const char*)(gb + (size_t)r * 128) + ck * 16;
                    asm volatile("cp.async.cg.shared.global [%0], [%1], 16;"
                                 :: "r"(base + r * 272 + ck * 16), "l"(g));
                }
            }
            asm volatile("cp.async.commit_group;");
        }
        // ---- store GEMM result to smem ----
#pragma unroll
        for (int i = 0; i < 2; i++)
#pragma unroll
            for (int j = 0; j < 2; j++)
                wmma::store_matrix_sync(&GB[(size_t)(wm + 16 * i) * 132 + wn + 16 * j],
                                        acc[i][j], 132, wmma::mem_row_major);
        __syncthreads();
        // ---- combine: 64x128 elems, each thread 8 float4 slots ----
#pragma unroll
        for (int it = 0; it < 8; it++) {
            int s = it * 256 + tid;        // 0..2047
            int n = s >> 5, c4 = (s & 31) * 4;
            const float* xgp = XG + (size_t)dir * NN * KK * H4
                             + ((size_t)(n0 + n) * KK + t) * H4 + gate * HH + c4;
            float4 gv = *(float4*)(GB + (size_t)n * 132 + c4);
            float4 xv = *(const float4*)xgp;
            float4 bv = *(const float4*)(bi + gate * HH + c4);
            float4 cv = *(const float4*)(bh + gate * HH + c4);
            float v0 = gv.x + xv.x + bv.x + cv.x;
            float v1 = gv.y + xv.y + bv.y + cv.y;
            float v2 = gv.z + xv.z + bv.z + cv.z;
            float v3 = gv.w + xv.w + bv.w + cv.w;
            float* sp = SB + (size_t)n * 128 + c4;
            size_t gidx = (size_t)dir * NN * HH + (size_t)(n0 + n) * HH + c4;
            if (gate == 0) {            // input gate
                sp[0] = 1.0f / (1.0f + expf(-v0));
                sp[1] = 1.0f / (1.0f + expf(-v1));
                sp[2] = 1.0f / (1.0f + expf(-v2));
                sp[3] = 1.0f / (1.0f + expf(-v3));
            } else if (gate == 2) {     // cell gate
                sp[0] *= tanhf(v0);
                sp[1] *= tanhf(v1);
                sp[2] *= tanhf(v2);
                sp[3] *= tanhf(v3);
            } else if (gate == 1) {     // forget gate
                float4 cp = *(float4*)(cbuf + gidx);
                float c0 = (1.0f / (1.0f + expf(-v0))) * cp.x + sp[0];
                float c1 = (1.0f / (1.0f + expf(-v1))) * cp.y + sp[1];
                float c2 = (1.0f / (1.0f + expf(-v2))) * cp.z + sp[2];
                float c3 = (1.0f / (1.0f + expf(-v3))) * cp.w + sp[3];
                sp[0] = c0; sp[1] = c1; sp[2] = c2; sp[3] = c3;
                *(float4*)(cbuf + gidx) = make_float4(c0, c1, c2, c3);
            } else {                    // output gate
                float h0 = (1.0f / (1.0f + expf(-v0))) * tanhf(sp[0]);
                float h1 = (1.0f / (1.0f + expf(-v1))) * tanhf(sp[1]);
                float h2 = (1.0f / (1.0f + expf(-v2))) * tanhf(sp[2]);
                float h3 = (1.0f / (1.0f + expf(-v3))) * tanhf(sp[3]);
                bf16 b0 = __float2bfloat16(h0), b1 = __float2bfloat16(h1);
                bf16 b2 = __float2bfloat16(h2), b3 = __float2bfloat16(h3);
                *(__nv_bfloat162*)(g_hb_hi + gidx)     = __halves2bfloat162(b0, b1);
                *(__nv_bfloat162*)(g_hb_hi + gidx + 2) = __halves2bfloat162(b2, b3);
                *(__nv_bfloat162*)(g_hb_lo + gidx)     = __halves2bfloat162(
                    __float2bfloat16(h0 - __bfloat162float(b0)),
                    __float2bfloat16(h1 - __bfloat162float(b1)));
                *(__nv_bfloat162*)(g_hb_lo + gidx + 2) = __halves2bfloat162(
                    __float2bfloat16(h2 - __bfloat162float(b2)),
                    __float2bfloat16(h3 - __bfloat162float(b3)));
                float* hout = dir ? hb : hf;
                *(float4*)(hout + ((size_t)(n0 + n) * KK + t) * HH + c4) =
                    make_float4(h0, h1, h2, h3);
            }
        }
        if (pi < 3) asm volatile("cp.async.wait_group 0;");
        __syncthreads();
    }
}

// ---------------- one-shot split of feat + all weight matrices ----------------
#define S_FEAT (NN * FF)
#define S_W    (KK * FF * HH)
__global__ void split_all(const float* __restrict__ feat, const float* __restrict__ w1,
                          const float* __restrict__ w2,
                          const float* __restrict__ wihf, const float* __restrict__ whhf,
                          const float* __restrict__ wihb, const float* __restrict__ whhb) {
    int i = blockIdx.x * 256 + threadIdx.x;
    const float* s; bf16 *h, *l; int off;
    if      (i < S_FEAT)             { s = feat; h = g_feat_hi; l = g_feat_lo; off = 0; }
    else if (i < S_FEAT + S_W)       { s = w1;   h = g_w1_hi;   l = g_w1_lo;   off = S_FEAT; }
    else if (i < S_FEAT + 2 * S_W)   { s = w2;   h = g_w2_hi;   l = g_w2_lo;   off = S_FEAT + S_W; }
    else if (i < S_FEAT + 3 * S_W)   { s = wihf; h = g_wihf_hi; l = g_wihf_lo; off = S_FEAT + 2 * S_W; }
    else if (i < S_FEAT + 4 * S_W)   { s = whhf; h = g_whhf_hi; l = g_whhf_lo; off = S_FEAT + 3 * S_W; }
    else if (i < S_FEAT + 5 * S_W)   { s = wihb; h = g_wihb_hi; l = g_wihb_lo; off = S_FEAT + 4 * S_W; }
    else if (i < S_FEAT + 6 * S_W)   { s = whhb; h = g_whhb_hi; l = g_whhb_lo; off = S_FEAT + 5 * S_W; }
    else return;
    int j = i - off;
    split1(s[j], h, l, j);
}

__global__ void split_ww() {
    int i = blockIdx.x * 256 + threadIdx.x;
    if (i < KK * HH * HH) split1(g_ww[i], g_ww_hi, g_ww_lo, i);
}

// bw[k][c] = sum_h b1[k][h] * w2[k][h][c]
__global__ __launch_bounds__(128)
void bw_kernel(const float* __restrict__ b1, const float* __restrict__ w2) {
    int k = blockIdx.x, c = threadIdx.x;
    const float* b = b1 + k * HH;
    const float* w = w2 + (size_t)k * HH * HH + c;
    float s0 = 0.f, s1 = 0.f, s2 = 0.f, s3 = 0.f;
#pragma unroll 8
    for (int h = 0; h < HH; h += 4) {
        s0 += b[h]     * w[(size_t)h * HH];
        s1 += b[h + 1] * w[(size_t)(h + 1) * HH];
        s2 += b[h + 2] * w[(size_t)(h + 2) * HH];
        s3 += b[h + 3] * w[(size_t)(h + 3) * HH];
    }
    g_bw[k * HH + c] = (s0 + s1) + (s2 + s3);
}

// ---------------- adjacency scan ----------------
__global__ void extract_kernel(const float* __restrict__ adj) {
    int n = blockIdx.x;
    __shared__ int scnt[KK];
    if (threadIdx.x < KK) scnt[threadIdx.x] = 0;
    __syncthreads();
    const float4* row = (const float4*)(adj + (size_t)n * NN * KK);
    for (int j = threadIdx.x; j < NN; j += blockDim.x) {
        float4 v = row[j];
        if (v.x > 0.5f) { int p = atomicAdd(&scnt[0], 1); if (p < MAXNB) g_cols[((size_t)(n * KK + 0)) * MAXNB + p] = j; }
        if (v.y > 0.5f) { int p = atomicAdd(&scnt[1], 1); if (p < MAXNB) g_cols[((size_t)(n * KK + 1)) * MAXNB + p] = j; }
        if (v.z > 0.5f) { int p = atomicAdd(&scnt[2], 1); if (p < MAXNB) g_cols[((size_t)(n * KK + 2)) * MAXNB + p] = j; }
        if (v.w > 0.5f) { int p = atomicAdd(&scnt[3], 1); if (p < MAXNB) g_cols[((size_t)(n * KK + 3)) * MAXNB + p] = j; }
    }
    __syncthreads();
    if (threadIdx.x < KK) {
        int m = scnt[threadIdx.x];
        if (m > MAXNB) m = MAXNB;
        g_cnt[n * KK + threadIdx.x] = m;
        g_dinv[n * KK + threadIdx.x] = rsqrtf((float)m + 1.0f);
    }
}

// ---------------- SpMM: 2 warps per (n,k), halved gather chain ----------------
__global__ __launch_bounds__(256)
void spmm_kernel(const float* __restrict__ x,
                 const float* __restrict__ bw, const float* __restrict__ b2,
                 float* __restrict__ out32,
                 bf16* __restrict__ ohi, bf16* __restrict__ olo,
                 long os_n, long os_k) {
    __shared__ int    scols[4][MAXNB];
    __shared__ float  swt[4][MAXNB];
    __shared__ float4 sacc[4][32];
    __shared__ float  spart[4];
    int warp = threadIdx.x >> 5, lane = threadIdx.x & 31;
    int nl = warp >> 1, sub = warp & 1;
    int n = blockIdx.x * 4 + nl;
    int k = blockIdx.y;
    int m = g_cnt[n * KK + k];
    float dn = g_dinv[n * KK + k];
    const int* cl = &g_cols[((size_t)(n * KK + k)) * MAXNB];

    float ssum = 0.0f;
    for (int i = lane + sub * 32; i < m; i += 64) {
        int j = cl[i];
        float wj = g_dinv[j * KK + k];
        scols[nl][i] = j;
        swt[nl][i] = wj;
        ssum += wj;
    }
#pragma unroll
    for (int o = 16; o; o >>= 1) ssum += __shfl_xor_sync(0xffffffffu, ssum, o);
    if (sub == 1 && lane == 0) spart[nl] = ssum;
    __syncthreads();

    const float* xk = x + (size_t)k * NN * HH;
    int c4 = lane * 4;
    float4 acc = make_float4(0.f, 0.f, 0.f, 0.f);
    if (sub == 0) {
        float4 xs = *(const float4*)(xk + (size_t)n * HH + c4);
        acc = make_float4(dn * xs.x, dn * xs.y, dn * xs.z, dn * xs.w);
    }
    int mh = (m + 1) >> 1;
    int lo = sub ? mh : 0;
    int hi = sub ? m : mh;
    int i = lo;
    for (; i + 8 <= hi; i += 8) {
        float4 v[8]; float wv[8];
#pragma unroll
        for (int u = 0; u < 8; u++) {
            wv[u] = swt[nl][i + u];
            v[u] = *(const float4*)(xk + (size_t)scols[nl][i + u] * HH + c4);
        }
#pragma unroll
        for (int u = 0; u < 8; u++) {
            acc.x += wv[u] * v[u].x; acc.y += wv[u] * v[u].y;
            acc.z += wv[u] * v[u].z; acc.w += wv[u] * v[u].w;
        }
    }
    for (; i < hi; i++) {
        float wj = swt[nl][i];
        float4 v = *(const float4*)(xk + (size_t)scols[nl][i] * HH + c4);
        acc.x += wj * v.x; acc.y += wj * v.y; acc.z += wj * v.z; acc.w += wj * v.w;
    }
    if (sub == 1) sacc[nl][lane] = acc;
    __syncthreads();
    if (sub == 1) return;

    float4 p = sacc[nl][lane];
    acc.x += p.x; acc.y += p.y; acc.z += p.z; acc.w += p.w;
    float ssum_tot = ssum + spart[nl];

    float4 r;
    if (bw) {
        float rn = dn * (dn + ssum_tot);
        float4 bwv = *(const float4*)(bw + k * HH + c4);
        float4 b2v = *(const float4*)(b2 + k * HH + c4);
        r = make_float4(dn * acc.x + rn * bwv.x + b2v.x,
                        dn * acc.y + rn * bwv.y + b2v.y,
                        dn * acc.z + rn * bwv.z + b2v.z,
                        dn * acc.w + rn * bwv.w + b2v.w);
    } else {
        r = make_float4(dn * acc.x, dn * acc.y, dn * acc.z, dn * acc.w);
    }
    size_t idx = (size_t)n * os_n + (size_t)k * os_k + c4;
    *(float4*)(out32 + idx) = r;
    if (ohi) {
        bf16 h0 = __float2bfloat16(r.x), h1 = __float2bfloat16(r.y);
        bf16 h2 = __float2bfloat16(r.z), h3 = __float2bfloat16(r.w);
        *(__nv_bfloat162*)(ohi + idx)     = __halves2bfloat162(h0, h1);
        *(__nv_bfloat162*)(ohi + idx + 2) = __halves2bfloat162(h2, h3);
        *(__nv_bfloat162*)(olo + idx)     = __halves2bfloat162(
            __float2bfloat16(r.x - __bfloat162float(h0)), __float2bfloat16(r.y - __bfloat162float(h1)));
        *(__nv_bfloat162*)(olo + idx + 2) = __halves2bfloat162(
            __float2bfloat16(r.z - __bfloat162float(h2)), __float2bfloat16(r.w - __bfloat162float(h3)));
    }
}

// ---------------- LSTM first-step gate (no recurrent term) ----------------
__global__ __launch_bounds__(256)
void lstm_gate0_kernel(const float* __restrict__ XG,
                       const float* __restrict__ bi_f, const float* __restrict__ bh_f,
                       const float* __restrict__ bi_b, const float* __restrict__ bh_b,
                       float* __restrict__ cbuf,
                       float* __restrict__ hf, float* __restrict__ hb) {
    int dir = blockIdx.y;
    int idx = blockIdx.x * 256 + threadIdx.x;
    int n = idx >> 5, q = (idx & 31) * 4;
    int t = dir ? (KK - 1) : 0;
    const float* xg = XG + (size_t)dir * NN * KK * H4 + ((size_t)n * KK + t) * H4;
    const float* bi = dir ? bi_b : bi_f;
    const float* bh = dir ? bh_b : bh_f;
    float4 vi = *(const float4*)(xg + q);
    float4 vf = *(const float4*)(xg + HH + q);
    float4 vg = *(const float4*)(xg + 2 * HH + q);
    float4 vo = *(const float4*)(xg + 3 * HH + q);
    float4 b0 = *(const float4*)(bi + q),          c0 = *(const float4*)(bh + q);
    float4 b1 = *(const float4*)(bi + HH + q),     c1 = *(const float4*)(bh + HH + q);
    float4 b2 = *(const float4*)(bi + 2 * HH + q), c2 = *(const float4*)(bh + 2 * HH + q);
    float4 b3 = *(const float4*)(bi + 3 * HH + q), c3 = *(const float4*)(bh + 3 * HH + q);
    vi.x += b0.x + c0.x; vi.y += b0.y + c0.y; vi.z += b0.z + c0.z; vi.w += b0.w + c0.w;
    vf.x += b1.x + c1.x; vf.y += b1.y + c1.y; vf.z += b1.z + c1.z; vf.w += b1.w + c1.w;
    vg.x += b2.x + c2.x; vg.y += b2.y + c2.y; vg.z += b2.z + c2.z; vg.w += b2.w + c2.w;
    vo.x += b3.x + c3.x; vo.y += b3.y + c3.y; vo.z += b3.z + c3.z; vo.w += b3.w + c3.w;
    size_t sidx = (size_t)dir * NN * HH + (size_t)n * HH + q;
    float4 cnew, hv;
#define GATE_COMP(E) { \
    float I = 1.0f / (1.0f + expf(-vi.E)); \
    float Fv = 1.0f / (1.0f + expf(-vf.E)); \
    float G = tanhf(vg.E); \
    float O = 1.0f / (1.0f + expf(-vo.E)); \
    float cn = I * G; (void)Fv; \
    cnew.E = cn; hv.E = O * tanhf(cn); }
    GATE_COMP(x) GATE_COMP(y) GATE_COMP(z) GATE_COMP(w)
#undef GATE_COMP
    *(float4*)(cbuf + sidx) = cnew;
    bf16 h0 = __float2bfloat16(hv.x), h1 = __float2bfloat16(hv.y);
    bf16 h2 = __float2bfloat16(hv.z), h3 = __float2bfloat16(hv.w);
    *(__nv_bfloat162*)(g_hb_hi + sidx)     = __halves2bfloat162(h0, h1);
    *(__nv_bfloat162*)(g_hb_hi + sidx + 2) = __halves2bfloat162(h2, h3);
    *(__nv_bfloat162*)(g_hb_lo + sidx)     = __halves2bfloat162(
        __float2bfloat16(hv.x - __bfloat162float(h0)), __float2bfloat16(hv.y - __bfloat162float(h1)));
    *(__nv_bfloat162*)(g_hb_lo + sidx + 2) = __halves2bfloat162(
        __float2bfloat16(hv.z - __bfloat162float(h2)), __float2bfloat16(hv.w - __bfloat162float(h3)));
    float* hout = dir ? hb : hf;
    *(float4*)(hout + ((size_t)n * KK + t) * HH + q) = hv;
}

// ---------------- attention + pooling + classifier + softmax ----------------
__global__ void final_kernel(const float* __restrict__ rw, const float* __restrict__ rb,
                             const float* __restrict__ ow, const float* __restrict__ ob,
                             float* __restrict__ out) {
    int n = blockIdx.x;
    int t = threadIdx.x;
    __shared__ float red[4];
    __shared__ float sattn[KK];
    __shared__ float sp[HH];
    __shared__ float sl[16];

    for (int k = 0; k < KK; k++) {
        float p = g_hfwd[((size_t)n * KK + k) * HH + t] * rw[t]
                + g_hbwd[((size_t)n * KK + k) * HH + t] * rw[HH + t];
        for (int o = 16; o; o >>= 1) p += __shfl_down_sync(0xffffffffu, p, o);
        if ((t & 31) == 0) red[t >> 5] = p;
        __syncthreads();
        if (t == 0) sattn[k] = red[0] + red[1] + red[2] + red[3] + rb[0];
        __syncthreads();
    }
    if (t == 0) {
        float m = sattn[0];
        for (int k = 1; k < KK; k++) m = fmaxf(m, sattn[k]);
        float s = 0.0f;
        for (int k = 0; k < KK; k++) { sattn[k] = expf(sattn[k] - m); s += sattn[k]; }
        float inv = 1.0f / s;
        for (int k = 0; k < KK; k++) sattn[k] *= inv;
    }
    __syncthreads();
    float pooled = 0.0f;
    for (int k = 0; k < KK; k++)
        pooled += sattn[k] * g_gnn[((size_t)n * KK + k) * HH + t];
    sp[t] = pooled;
    __syncthreads();
    int w = t >> 5, lane = t & 31;
    for (int c = w; c < CC; c += 4) {
        float s = sp[lane] * ow[c * HH + lane]
                + sp[lane + 32] * ow[c * HH + lane + 32]
                + sp[lane + 64] * ow[c * HH + lane + 64]
                + sp[lane + 96] * ow[c * HH + lane + 96];
        for (int o = 16; o; o >>= 1) s += __shfl_down_sync(0xffffffffu, s, o);
        if (lane == 0) sl[c] = s + ob[c];
    }
    __syncthreads();
    if (t == 0) {
        float m = sl[0];
        for (int c = 1; c < CC; c++) m = fmaxf(m, sl[c]);
        float s = 0.0f;
        for (int c = 0; c < CC; c++) { sl[c] = expf(sl[c] - m); s += sl[c]; }
        float inv = 1.0f / s;
        for (int c = 0; c < CC; c++) out[(size_t)n * CC + c] = sl[c] * inv;
    }
}

// ---------------- host orchestration ----------------
extern "C" void kernel_launch(void* const* d_in, const int* in_sizes, int n_in,
                              void* d_out, int out_size) {
    const float* feat  = (const float*)d_in[0];
    const float* adj   = (const float*)d_in[1];
    const float* w1    = (const float*)d_in[2];
    const float* b1    = (const float*)d_in[3];
    const float* w2    = (const float*)d_in[4];
    const float* b2    = (const float*)d_in[5];
    const float* wih_f = (const float*)d_in[6];
    const float* whh_f = (const float*)d_in[7];
    const float* bih_f = (const float*)d_in[8];
    const float* bhh_f = (const float*)d_in[9];
    const float* wih_b = (const float*)d_in[10];
    const float* whh_b = (const float*)d_in[11];
    const float* bih_b = (const float*)d_in[12];
    const float* bhh_b = (const float*)d_in[13];
    const float* rw    = (const float*)d_in[14];
    const float* rb    = (const float*)d_in[15];
    const float* ow    = (const float*)d_in[16];
    const float* ob    = (const float*)d_in[17];
    float* out = (float*)d_out;

    float *dT, *dh1f, *dww, *dbw, *dgnn, *dXG, *dcbuf, *dhf, *dhb;
    cudaGetSymbolAddress((void**)&dT,    g_T);
    cudaGetSymbolAddress((void**)&dh1f,  g_h1f);
    cudaGetSymbolAddress((void**)&dww,   g_ww);
    cudaGetSymbolAddress((void**)&dbw,   g_bw);
    cudaGetSymbolAddress((void**)&dgnn,  g_gnn);
    cudaGetSymbolAddress((void**)&dXG,   g_XG);
    cudaGetSymbolAddress((void**)&dcbuf, g_cbuf);
    cudaGetSymbolAddress((void**)&dhf,   g_hfwd);
    cudaGetSymbolAddress((void**)&dhb,   g_hbwd);

    bf16 *feat_hi, *feat_lo, *w1_hi, *w1_lo, *w2_hi, *w2_lo, *ww_hi, *ww_lo;
    bf16 *wihf_hi, *wihf_lo, *wihb_hi, *wihb_lo;
    bf16 *gnn_hi, *gnn_lo;
    cudaGetSymbolAddress((void**)&feat_hi, g_feat_hi); cudaGetSymbolAddress((void**)&feat_lo, g_feat_lo);
    cudaGetSymbolAddress((void**)&w1_hi,   g_w1_hi);   cudaGetSymbolAddress((void**)&w1_lo,   g_w1_lo);
    cudaGetSymbolAddress((void**)&w2_hi,   g_w2_hi);   cudaGetSymbolAddress((void**)&w2_lo,   g_w2_lo);
    cudaGetSymbolAddress((void**)&ww_hi,   g_ww_hi);   cudaGetSymbolAddress((void**)&ww_lo,   g_ww_lo);
    cudaGetSymbolAddress((void**)&wihf_hi, g_wihf_hi); cudaGetSymbolAddress((void**)&wihf_lo, g_wihf_lo);
    cudaGetSymbolAddress((void**)&wihb_hi, g_wihb_hi); cudaGetSymbolAddress((void**)&wihb_lo, g_wihb_lo);
    cudaGetSymbolAddress((void**)&gnn_hi,  g_gnn_hi);  cudaGetSymbolAddress((void**)&gnn_lo,  g_gnn_lo);

    static cudaStream_t s2 = nullptr;
    static cudaEvent_t evFork = nullptr, evJoin = nullptr;
    if (!s2) {
        cudaStreamCreateWithFlags(&s2, cudaStreamNonBlocking);
        cudaEventCreateWithFlags(&evFork, cudaEventDisableTiming);
        cudaEventCreateWithFlags(&evJoin, cudaEventDisableTiming);
        cudaFuncSetAttribute((const void*)wmma_gemm<0, 1>,
                             cudaFuncAttributeMaxDynamicSharedMemorySize, SMEM_BYTES);
        cudaFuncSetAttribute((const void*)wmma_gemm<1, 4>,
                             cudaFuncAttributeMaxDynamicSharedMemorySize, SMEM_BYTES);
        cudaFuncSetAttribute((const void*)lstm_fused_kernel,
                             cudaFuncAttributeMaxDynamicSharedMemorySize, FUSED_SMEM);
    }

    const long NH = (long)NN * HH;
    const long XGZ = (long)NN * KK * H4;

    // --- fork: extract (DRAM-bound, independent) on side stream ---
    cudaEventRecord(evFork, 0);
    cudaStreamWaitEvent(s2, evFork, 0);
    extract_kernel<<<NN, 256, 0, s2>>>(adj);
    cudaEventRecord(evJoin, s2);

    // --- main stream (independent of extract): splits, ww = w1@w2,
    //     bw = b1@w2, P = feat @ ww ---
    split_all<<<(S_FEAT + 6 * S_W) / 256, 256>>>(feat, w1, w2, wih_f, whh_f, wih_b, whh_b);
    bw_kernel<<<KK, 128>>>(b1, w2);
    wmma_gemm<0, 1><<<dim3(2, 1, KK), 256, SMEM_BYTES>>>(
        w1_hi, w1_lo, 128, w2_hi, w2_lo, nullptr, nullptr, (long)HH * HH, HH,
        dww, (long)HH * HH, HH);
    split_ww<<<(KK * HH * HH) / 256, 256>>>();
    wmma_gemm<0, 1><<<dim3(2, NN / 128, KK), 256, SMEM_BYTES>>>(
        feat_hi, feat_lo, 0, ww_hi, ww_lo, nullptr, nullptr, (long)HH * HH, HH,
        dT, NH, HH);

    // --- join: spmm needs neighbor lists ---
    cudaStreamWaitEvent(0, evJoin, 0);

    // double aggregation
    spmm_kernel<<<dim3(NN / 4, KK), 256>>>(dT, nullptr, nullptr, dh1f, nullptr, nullptr, HH, NH);
    spmm_kernel<<<dim3(NN / 4, KK), 256>>>(dh1f, dbw, b2, dgnn, gnn_hi, gnn_lo, (long)KK * HH, HH);

    // LSTM input precompute (A staged once per 256 output cols)
    wmma_gemm<1, 4><<<dim3(2, (NN * KK) / 128, 2), 256, SMEM_BYTES>>>(
        gnn_hi, gnn_lo, 0, wihf_hi, wihf_lo, wihb_hi, wihb_lo, 0, HH, dXG, XGZ, H4);

    // Bidirectional LSTM: step 0 gate-only, steps 1..3 fused GEMM+gate
    lstm_gate0_kernel<<<dim3((NN * 32) / 256, 2), 256>>>(
        dXG, bih_f, bhh_f, bih_b, bhh_b, dcbuf, dhf, dhb);
    for (int step = 1; step < KK; step++)
        lstm_fused_kernel<<<dim3(NN / 64, 2), 256, FUSED_SMEM>>>(
            dXG, bih_f, bhh_f, bih_b, bhh_b, dcbuf, dhf, dhb, step);

    // attention + pooling + classifier
    final_kernel<<<NN, 128>>>(rw, rb, ow, ob, out);

    (void)in_sizes; (void)n_in; (void)out_size;
}

// round 13
// speedup vs baseline: 1.1627x; 1.1627x over previous
#include <cuda_runtime.h>
#include <cuda_bf16.h>
#include <mma.h>
#include <math.h>
#include <cstdint>

using namespace nvcuda;

// Problem constants
#define NN 4096
#define FF 128
#define HH 128
#define KK 4
#define CC 10
#define H4 512
#define MAXNB 256

typedef __nv_bfloat16 bf16;

// ---------------- scratch (device globals; no runtime allocation) ----------------
__device__ float g_dinv[NN * KK];
__device__ int   g_cnt[NN * KK];
__device__ int   g_cols[(size_t)NN * KK * MAXNB];
__device__ float g_T[(size_t)KK * NN * HH];
__device__ float g_gnn[(size_t)NN * KK * HH];
__device__ float g_XG[(size_t)2 * NN * KK * H4];
__device__ float g_Hh[(size_t)2 * NN * H4];
__device__ float g_cbuf[(size_t)2 * NN * HH];
__device__ float g_hfwd[(size_t)NN * KK * HH];
__device__ float g_hbwd[(size_t)NN * KK * HH];

// pre-split bf16 hi/lo buffers
__device__ bf16 g_feat_hi[NN * FF],            g_feat_lo[NN * FF];
__device__ bf16 g_w1_hi[KK * FF * HH],         g_w1_lo[KK * FF * HH];
__device__ bf16 g_w2_hi[KK * HH * HH],         g_w2_lo[KK * HH * HH];
__device__ bf16 g_wihf_hi[H4 * HH],            g_wihf_lo[H4 * HH];
__device__ bf16 g_whhf_hi[H4 * HH],            g_whhf_lo[H4 * HH];
__device__ bf16 g_wihb_hi[H4 * HH],            g_wihb_lo[H4 * HH];
__device__ bf16 g_whhb_hi[H4 * HH],            g_whhb_lo[H4 * HH];
__device__ bf16 g_h1_hi[(size_t)KK * NN * HH], g_h1_lo[(size_t)KK * NN * HH];
__device__ bf16 g_gnn_hi[(size_t)NN * KK * HH],g_gnn_lo[(size_t)NN * KK * HH];
__device__ bf16 g_hb_hi[(size_t)2 * NN * HH],  g_hb_lo[(size_t)2 * NN * HH];

__device__ __forceinline__ uint32_t smem_u32(const void* p) {
    uint32_t a;
    asm("{ .reg .u64 t; cvta.to.shared.u64 t, %1; cvt.u32.u64 %0, t; }" : "=r"(a) : "l"(p));
    return a;
}

__device__ __forceinline__ void split1(float x, bf16* hi, bf16* lo, size_t idx) {
    bf16 h = __float2bfloat16(x);
    hi[idx] = h;
    lo[idx] = __float2bfloat16(x - __bfloat162float(h));
}

// ============================================================================
// wmma bf16 split-precision GEMM: 128x64 tiles (x NCH N-chunks per block,
// A staged once), 256 thr, cp.async staging, 2 blocks/SM.
// BCOL=0: B is [128 x ldb] K-major, take cols bn..bn+63
// BCOL=1: B is [N x 128] row-major, used as B^T, take rows bn..bn+63
// ============================================================================
#define LDA 136
#define A_E (128 * LDA)
#define B_E 9216
#define SMEM_BYTES ((2 * A_E + 2 * B_E) * 2)

template <int BCOL, int NCH>
__global__ __launch_bounds__(256, 2)
void wmma_gemm(const bf16* __restrict__ Ahi_g, const bf16* __restrict__ Alo_g,
               long a_zrows,
               const bf16* __restrict__ Bhi0, const bf16* __restrict__ Blo0,
               const bf16* __restrict__ Bhi1, const bf16* __restrict__ Blo1,
               long b_zstride, int ldb,
               float* __restrict__ C, long c_zstride, int ldc) {
    extern __shared__ bf16 sm[];
    bf16* Ahi = sm;
    bf16* Alo = sm + A_E;
    bf16* Bhi = sm + 2 * A_E;
    bf16* Blo = sm + 2 * A_E + B_E;

    int tid = threadIdx.x;
    int z = blockIdx.z;
    long arow0 = (long)blockIdx.y * 128 + (long)z * a_zrows;
    const bf16* bhp = (Bhi1 && z) ? Bhi1 : (Bhi0 + (size_t)z * b_zstride);
    const bf16* blp = (Blo1 && z) ? Blo1 : (Blo0 + (size_t)z * b_zstride);

    uint32_t sb = smem_u32(sm);
    const bf16* asrc0 = Ahi_g + arow0 * 128;
    const bf16* asrc1 = Alo_g + arow0 * 128;
#pragma unroll
    for (int t = 0; t < 2; t++) {
        const bf16* gb = t ? asrc1 : asrc0;
        uint32_t base = sb + t * (A_E * 2);
#pragma unroll
        for (int it = 0; it < 8; it++) {
            int i = it * 256 + tid;
            int r = i >> 4, ck = i & 15;
            const char* g = (const char*)(gb + (size_t)r * 128) + ck * 16;
            uint32_t s = base + r * 272 + ck * 16;
            asm volatile("cp.async.cg.shared.global [%0], [%1], 16;" :: "r"(s), "l"(g));
        }
    }

    int w = tid >> 5;
    int wm = (w & 3) * 32;
    int wn = (w >> 2) * 32;

    for (int ch = 0; ch < NCH; ch++) {
        int bn = (blockIdx.x * NCH + ch) * 64;
        // ---- stage B chunk ----
        if (!BCOL) {
#pragma unroll
            for (int t = 0; t < 2; t++) {
                const bf16* gb = (t ? blp : bhp) + bn;
                uint32_t base = sb + (2 * A_E + t * B_E) * 2;
#pragma unroll
                for (int it = 0; it < 4; it++) {
                    int i = it * 256 + tid;
                    int r = i >> 3, ck = i & 7;
                    const char* g = (const char*)(gb + (size_t)r * ldb) + ck * 16;
                    uint32_t s = base + r * 144 + ck * 16;
                    asm volatile("cp.async.cg.shared.global [%0], [%1], 16;" :: "r"(s), "l"(g));
                }
            }
        } else {
#pragma unroll
            for (int t = 0; t < 2; t++) {
                const bf16* gb = (t ? blp : bhp) + (size_t)bn * 128;
                uint32_t base = sb + (2 * A_E + t * B_E) * 2;
#pragma unroll
                for (int it = 0; it < 4; it++) {
                    int i = it * 256 + tid;
                    int r = i >> 4, ck = i & 15;
                    const char* g = (const char*)(gb + (size_t)r * 128) + ck * 16;
                    uint32_t s = base + r * 272 + ck * 16;
                    asm volatile("cp.async.cg.shared.global [%0], [%1], 16;" :: "r"(s), "l"(g));
                }
            }
        }
        asm volatile("cp.async.commit_group;");
        asm volatile("cp.async.wait_group 0;");
        __syncthreads();

        wmma::fragment<wmma::accumulator, 16, 16, 16, float> acc[2][2];
#pragma unroll
        for (int i = 0; i < 2; i++)
#pragma unroll
            for (int j = 0; j < 2; j++)
                wmma::fill_fragment(acc[i][j], 0.0f);

#pragma unroll
        for (int kk = 0; kk < 128; kk += 16) {
            wmma::fragment<wmma::matrix_a, 16, 16, 16, bf16, wmma::row_major> ah[2], al[2];
#pragma unroll
            for (int i = 0; i < 2; i++) {
                wmma::load_matrix_sync(ah[i], &Ahi[(wm + 16 * i) * LDA + kk], LDA);
                wmma::load_matrix_sync(al[i], &Alo[(wm + 16 * i) * LDA + kk], LDA);
            }
            if (!BCOL) {
                wmma::fragment<wmma::matrix_b, 16, 16, 16, bf16, wmma::row_major> bh[2], bl[2];
#pragma unroll
                for (int j = 0; j < 2; j++) {
                    wmma::load_matrix_sync(bh[j], &Bhi[kk * 72 + wn + 16 * j], 72);
                    wmma::load_matrix_sync(bl[j], &Blo[kk * 72 + wn + 16 * j], 72);
                }
#pragma unroll
                for (int i = 0; i < 2; i++)
#pragma unroll
                    for (int j = 0; j < 2; j++) {
                        wmma::mma_sync(acc[i][j], ah[i], bh[j], acc[i][j]);
                        wmma::mma_sync(acc[i][j], ah[i], bl[j], acc[i][j]);
                        wmma::mma_sync(acc[i][j], al[i], bh[j], acc[i][j]);
                    }
            } else {
                wmma::fragment<wmma::matrix_b, 16, 16, 16, bf16, wmma::col_major> bh[2], bl[2];
#pragma unroll
                for (int j = 0; j < 2; j++) {
                    wmma::load_matrix_sync(bh[j], &Bhi[(wn + 16 * j) * 136 + kk], 136);
                    wmma::load_matrix_sync(bl[j], &Blo[(wn + 16 * j) * 136 + kk], 136);
                }
#pragma unroll
                for (int i = 0; i < 2; i++)
#pragma unroll
                    for (int j = 0; j < 2; j++) {
                        wmma::mma_sync(acc[i][j], ah[i], bh[j], acc[i][j]);
                        wmma::mma_sync(acc[i][j], ah[i], bl[j], acc[i][j]);
                        wmma::mma_sync(acc[i][j], al[i], bh[j], acc[i][j]);
                    }
            }
        }

        float* Cp = C + (size_t)z * c_zstride + ((size_t)blockIdx.y * 128) * ldc + bn;
#pragma unroll
        for (int i = 0; i < 2; i++)
#pragma unroll
            for (int j = 0; j < 2; j++)
                wmma::store_matrix_sync(&Cp[(size_t)(wm + 16 * i) * ldc + wn + 16 * j],
                                        acc[i][j], ldc, wmma::mem_row_major);
        if (ch + 1 < NCH) __syncthreads();
    }
}

// ---------------- one-shot split of feat + all weight matrices ----------------
#define S_FEAT (NN * FF)
#define S_W    (KK * FF * HH)
__global__ void split_all(const float* __restrict__ feat, const float* __restrict__ w1,
                          const float* __restrict__ w2,
                          const float* __restrict__ wihf, const float* __restrict__ whhf,
                          const float* __restrict__ wihb, const float* __restrict__ whhb) {
    int i = blockIdx.x * 256 + threadIdx.x;
    const float* s; bf16 *h, *l; int off;
    if      (i < S_FEAT)             { s = feat; h = g_feat_hi; l = g_feat_lo; off = 0; }
    else if (i < S_FEAT + S_W)       { s = w1;   h = g_w1_hi;   l = g_w1_lo;   off = S_FEAT; }
    else if (i < S_FEAT + 2 * S_W)   { s = w2;   h = g_w2_hi;   l = g_w2_lo;   off = S_FEAT + S_W; }
    else if (i < S_FEAT + 3 * S_W)   { s = wihf; h = g_wihf_hi; l = g_wihf_lo; off = S_FEAT + 2 * S_W; }
    else if (i < S_FEAT + 4 * S_W)   { s = whhf; h = g_whhf_hi; l = g_whhf_lo; off = S_FEAT + 3 * S_W; }
    else if (i < S_FEAT + 5 * S_W)   { s = wihb; h = g_wihb_hi; l = g_wihb_lo; off = S_FEAT + 4 * S_W; }
    else if (i < S_FEAT + 6 * S_W)   { s = whhb; h = g_whhb_hi; l = g_whhb_lo; off = S_FEAT + 5 * S_W; }
    else return;
    int j = i - off;
    split1(s[j], h, l, j);
}

// ---------------- adjacency scan: build neighbor lists + dinv ----------------
__global__ void extract_kernel(const float* __restrict__ adj) {
    int n = blockIdx.x;
    __shared__ int scnt[KK];
    if (threadIdx.x < KK) scnt[threadIdx.x] = 0;
    __syncthreads();
    const float4* row = (const float4*)(adj + (size_t)n * NN * KK);
    for (int j = threadIdx.x; j < NN; j += blockDim.x) {
        float4 v = row[j];
        if (v.x > 0.5f) { int p = atomicAdd(&scnt[0], 1); if (p < MAXNB) g_cols[((size_t)(n * KK + 0)) * MAXNB + p] = j; }
        if (v.y > 0.5f) { int p = atomicAdd(&scnt[1], 1); if (p < MAXNB) g_cols[((size_t)(n * KK + 1)) * MAXNB + p] = j; }
        if (v.z > 0.5f) { int p = atomicAdd(&scnt[2], 1); if (p < MAXNB) g_cols[((size_t)(n * KK + 2)) * MAXNB + p] = j; }
        if (v.w > 0.5f) { int p = atomicAdd(&scnt[3], 1); if (p < MAXNB) g_cols[((size_t)(n * KK + 3)) * MAXNB + p] = j; }
    }
    __syncthreads();
    if (threadIdx.x < KK) {
        int m = scnt[threadIdx.x];
        if (m > MAXNB) m = MAXNB;
        g_cnt[n * KK + threadIdx.x] = m;
        g_dinv[n * KK + threadIdx.x] = rsqrtf((float)m + 1.0f);
    }
}

// ---------------- SpMM: warp per (n,k), lane owns 4 channels, 8-wide gather ----
__global__ __launch_bounds__(256)
void spmm_kernel(const float* __restrict__ x, const float* __restrict__ bias,
                 float* __restrict__ out32,
                 bf16* __restrict__ ohi, bf16* __restrict__ olo,
                 long os_n, long os_k) {
    __shared__ int   scols[8][MAXNB];
    __shared__ float swt[8][MAXNB];
    int w = threadIdx.x >> 5, lane = threadIdx.x & 31;
    int n = blockIdx.x * 8 + w;
    int k = blockIdx.y;
    int m = g_cnt[n * KK + k];
    float dn = g_dinv[n * KK + k];
    const int* cl = &g_cols[((size_t)(n * KK + k)) * MAXNB];
    for (int i = lane; i < m; i += 32) {
        int j = cl[i];
        scols[w][i] = j;
        swt[w][i] = g_dinv[j * KK + k];
    }
    __syncwarp();
    const float* xk = x + (size_t)k * NN * HH;
    int c4 = lane * 4;
    float4 xs = *(const float4*)(xk + (size_t)n * HH + c4);
    float4 acc = make_float4(dn * xs.x, dn * xs.y, dn * xs.z, dn * xs.w);
    int i = 0;
    for (; i + 8 <= m; i += 8) {
        float4 v[8]; float wv[8];
#pragma unroll
        for (int u = 0; u < 8; u++) {
            wv[u] = swt[w][i + u];
            v[u] = *(const float4*)(xk + (size_t)scols[w][i + u] * HH + c4);
        }
#pragma unroll
        for (int u = 0; u < 8; u++) {
            acc.x += wv[u] * v[u].x; acc.y += wv[u] * v[u].y;
            acc.z += wv[u] * v[u].z; acc.w += wv[u] * v[u].w;
        }
    }
    for (; i < m; i++) {
        float wj = swt[w][i];
        float4 v = *(const float4*)(xk + (size_t)scols[w][i] * HH + c4);
        acc.x += wj * v.x; acc.y += wj * v.y; acc.z += wj * v.z; acc.w += wj * v.w;
    }
    float4 bv = *(const float4*)(bias + k * HH + c4);
    float4 r = make_float4(dn * acc.x + bv.x, dn * acc.y + bv.y,
                           dn * acc.z + bv.z, dn * acc.w + bv.w);
    size_t idx = (size_t)n * os_n + (size_t)k * os_k + c4;
    if (out32) *(float4*)(out32 + idx) = r;
    bf16 h0 = __float2bfloat16(r.x), h1 = __float2bfloat16(r.y);
    bf16 h2 = __float2bfloat16(r.z), h3 = __float2bfloat16(r.w);
    *(__nv_bfloat162*)(ohi + idx)     = __halves2bfloat162(h0, h1);
    *(__nv_bfloat162*)(ohi + idx + 2) = __halves2bfloat162(h2, h3);
    *(__nv_bfloat162*)(olo + idx)     = __halves2bfloat162(
        __float2bfloat16(r.x - __bfloat162float(h0)), __float2bfloat16(r.y - __bfloat162float(h1)));
    *(__nv_bfloat162*)(olo + idx + 2) = __halves2bfloat162(
        __float2bfloat16(r.z - __bfloat162float(h2)), __float2bfloat16(r.w - __bfloat162float(h3)));
}

// ---------------- LSTM gate fusion, float4, both dirs batched (blockIdx.y = dir) ----------------
__global__ __launch_bounds__(256)
void lstm_gate_kernel(const float* __restrict__ XG, const float* __restrict__ Hh,
                      const float* __restrict__ bi_f, const float* __restrict__ bh_f,
                      const float* __restrict__ bi_b, const float* __restrict__ bh_b,
                      float* __restrict__ cbuf,
                      float* __restrict__ hf, float* __restrict__ hb, int step) {
    int dir = blockIdx.y;
    int idx = blockIdx.x * 256 + threadIdx.x;   // 0 .. NN*32-1
    int n = idx >> 5, q = (idx & 31) * 4;
    int t = dir ? (KK - 1 - step) : step;
    int first = (step == 0);
    const float* xg = XG + (size_t)dir * NN * KK * H4 + ((size_t)n * KK + t) * H4;
    const float* bi = dir ? bi_b : bi_f;
    const float* bh = dir ? bh_b : bh_f;
    float4 vi = *(const float4*)(xg + q);
    float4 vf = *(const float4*)(xg + HH + q);
    float4 vg = *(const float4*)(xg + 2 * HH + q);
    float4 vo = *(const float4*)(xg + 3 * HH + q);
    float4 b0 = *(const float4*)(bi + q),          c0 = *(const float4*)(bh + q);
    float4 b1 = *(const float4*)(bi + HH + q),     c1 = *(const float4*)(bh + HH + q);
    float4 b2 = *(const float4*)(bi + 2 * HH + q), c2 = *(const float4*)(bh + 2 * HH + q);
    float4 b3 = *(const float4*)(bi + 3 * HH + q), c3 = *(const float4*)(bh + 3 * HH + q);
    vi.x += b0.x + c0.x; vi.y += b0.y + c0.y; vi.z += b0.z + c0.z; vi.w += b0.w + c0.w;
    vf.x += b1.x + c1.x; vf.y += b1.y + c1.y; vf.z += b1.z + c1.z; vf.w += b1.w + c1.w;
    vg.x += b2.x + c2.x; vg.y += b2.y + c2.y; vg.z += b2.z + c2.z; vg.w += b2.w + c2.w;
    vo.x += b3.x + c3.x; vo.y += b3.y + c3.y; vo.z += b3.z + c3.z; vo.w += b3.w + c3.w;
    if (!first) {
        const float* hh = Hh + (size_t)dir * NN * H4 + (size_t)n * H4;
        float4 h0 = *(const float4*)(hh + q);
        float4 h1 = *(const float4*)(hh + HH + q);
        float4 h2 = *(const float4*)(hh + 2 * HH + q);
        float4 h3 = *(const float4*)(hh + 3 * HH + q);
        vi.x += h0.x; vi.y += h0.y; vi.z += h0.z; vi.w += h0.w;
        vf.x += h1.x; vf.y += h1.y; vf.z += h1.z; vf.w += h1.w;
        vg.x += h2.x; vg.y += h2.y; vg.z += h2.z; vg.w += h2.w;
        vo.x += h3.x; vo.y += h3.y; vo.z += h3.z; vo.w += h3.w;
    }
    size_t sidx = (size_t)dir * NN * HH + (size_t)n * HH + q;
    float4 cprev = first ? make_float4(0.f, 0.f, 0.f, 0.f) : *(const float4*)(cbuf + sidx);
    float4 cnew, hv;
#define GATE_COMP(E) { \
    float I = 1.0f / (1.0f + expf(-vi.E)); \
    float Fv = 1.0f / (1.0f + expf(-vf.E)); \
    float G = tanhf(vg.E); \
    float O = 1.0f / (1.0f + expf(-vo.E)); \
    float cn = Fv * cprev.E + I * G; \
    cnew.E = cn; hv.E = O * tanhf(cn); }
    GATE_COMP(x) GATE_COMP(y) GATE_COMP(z) GATE_COMP(w)
#undef GATE_COMP
    *(float4*)(cbuf + sidx) = cnew;
    bf16 h0 = __float2bfloat16(hv.x), h1 = __float2bfloat16(hv.y);
    bf16 h2 = __float2bfloat16(hv.z), h3 = __float2bfloat16(hv.w);
    *(__nv_bfloat162*)(g_hb_hi + sidx)     = __halves2bfloat162(h0, h1);
    *(__nv_bfloat162*)(g_hb_hi + sidx + 2) = __halves2bfloat162(h2, h3);
    *(__nv_bfloat162*)(g_hb_lo + sidx)     = __halves2bfloat162(
        __float2bfloat16(hv.x - __bfloat162float(h0)), __float2bfloat16(hv.y - __bfloat162float(h1)));
    *(__nv_bfloat162*)(g_hb_lo + sidx + 2) = __halves2bfloat162(
        __float2bfloat16(hv.z - __bfloat162float(h2)), __float2bfloat16(hv.w - __bfloat162float(h3)));
    float* hout = dir ? hb : hf;
    *(float4*)(hout + ((size_t)n * KK + t) * HH + q) = hv;
}

// ---------------- attention + pooling + classifier + softmax ----------------
__global__ void final_kernel(const float* __restrict__ rw, const float* __restrict__ rb,
                             const float* __restrict__ ow, const float* __restrict__ ob,
                             float* __restrict__ out) {
    int n = blockIdx.x;
    int t = threadIdx.x;
    __shared__ float red[4];
    __shared__ float sattn[KK];
    __shared__ float sp[HH];
    __shared__ float sl[16];

    for (int k = 0; k < KK; k++) {
        float p = g_hfwd[((size_t)n * KK + k) * HH + t] * rw[t]
                + g_hbwd[((size_t)n * KK + k) * HH + t] * rw[HH + t];
        for (int o = 16; o; o >>= 1) p += __shfl_down_sync(0xffffffffu, p, o);
        if ((t & 31) == 0) red[t >> 5] = p;
        __syncthreads();
        if (t == 0) sattn[k] = red[0] + red[1] + red[2] + red[3] + rb[0];
        __syncthreads();
    }
    if (t == 0) {
        float m = sattn[0];
        for (int k = 1; k < KK; k++) m = fmaxf(m, sattn[k]);
        float s = 0.0f;
        for (int k = 0; k < KK; k++) { sattn[k] = expf(sattn[k] - m); s += sattn[k]; }
        float inv = 1.0f / s;
        for (int k = 0; k < KK; k++) sattn[k] *= inv;
    }
    __syncthreads();
    float pooled = 0.0f;
    for (int k = 0; k < KK; k++)
        pooled += sattn[k] * g_gnn[((size_t)n * KK + k) * HH + t];
    sp[t] = pooled;
    __syncthreads();
    int w = t >> 5, lane = t & 31;
    for (int c = w; c < CC; c += 4) {
        float s = sp[lane] * ow[c * HH + lane]
                + sp[lane + 32] * ow[c * HH + lane + 32]
                + sp[lane + 64] * ow[c * HH + lane + 64]
                + sp[lane + 96] * ow[c * HH + lane + 96];
        for (int o = 16; o; o >>= 1) s += __shfl_down_sync(0xffffffffu, s, o);
        if (lane == 0) sl[c] = s + ob[c];
    }
    __syncthreads();
    if (t == 0) {
        float m = sl[0];
        for (int c = 1; c < CC; c++) m = fmaxf(m, sl[c]);
        float s = 0.0f;
        for (int c = 0; c < CC; c++) { sl[c] = expf(sl[c] - m); s += sl[c]; }
        float inv = 1.0f / s;
        for (int c = 0; c < CC; c++) out[(size_t)n * CC + c] = sl[c] * inv;
    }
}

// ---------------- host orchestration ----------------
extern "C" void kernel_launch(void* const* d_in, const int* in_sizes, int n_in,
                              void* d_out, int out_size) {
    const float* feat  = (const float*)d_in[0];
    const float* adj   = (const float*)d_in[1];
    const float* w1    = (const float*)d_in[2];
    const float* b1    = (const float*)d_in[3];
    const float* w2    = (const float*)d_in[4];
    const float* b2    = (const float*)d_in[5];
    const float* wih_f = (const float*)d_in[6];
    const float* whh_f = (const float*)d_in[7];
    const float* bih_f = (const float*)d_in[8];
    const float* bhh_f = (const float*)d_in[9];
    const float* wih_b = (const float*)d_in[10];
    const float* whh_b = (const float*)d_in[11];
    const float* bih_b = (const float*)d_in[12];
    const float* bhh_b = (const float*)d_in[13];
    const float* rw    = (const float*)d_in[14];
    const float* rb    = (const float*)d_in[15];
    const float* ow    = (const float*)d_in[16];
    const float* ob    = (const float*)d_in[17];
    float* out = (float*)d_out;

    float *dT, *dgnn, *dXG, *dHh, *dcbuf, *dhf, *dhb;
    cudaGetSymbolAddress((void**)&dT,    g_T);
    cudaGetSymbolAddress((void**)&dgnn,  g_gnn);
    cudaGetSymbolAddress((void**)&dXG,   g_XG);
    cudaGetSymbolAddress((void**)&dHh,   g_Hh);
    cudaGetSymbolAddress((void**)&dcbuf, g_cbuf);
    cudaGetSymbolAddress((void**)&dhf,   g_hfwd);
    cudaGetSymbolAddress((void**)&dhb,   g_hbwd);

    bf16 *feat_hi, *feat_lo, *w1_hi, *w1_lo, *w2_hi, *w2_lo;
    bf16 *wihf_hi, *wihf_lo, *whhf_hi, *whhf_lo, *wihb_hi, *wihb_lo, *whhb_hi, *whhb_lo;
    bf16 *h1_hi, *h1_lo, *gnn_hi, *gnn_lo, *hb_hi, *hb_lo;
    cudaGetSymbolAddress((void**)&feat_hi, g_feat_hi); cudaGetSymbolAddress((void**)&feat_lo, g_feat_lo);
    cudaGetSymbolAddress((void**)&w1_hi,   g_w1_hi);   cudaGetSymbolAddress((void**)&w1_lo,   g_w1_lo);
    cudaGetSymbolAddress((void**)&w2_hi,   g_w2_hi);   cudaGetSymbolAddress((void**)&w2_lo,   g_w2_lo);
    cudaGetSymbolAddress((void**)&wihf_hi, g_wihf_hi); cudaGetSymbolAddress((void**)&wihf_lo, g_wihf_lo);
    cudaGetSymbolAddress((void**)&whhf_hi, g_whhf_hi); cudaGetSymbolAddress((void**)&whhf_lo, g_whhf_lo);
    cudaGetSymbolAddress((void**)&wihb_hi, g_wihb_hi); cudaGetSymbolAddress((void**)&wihb_lo, g_wihb_lo);
    cudaGetSymbolAddress((void**)&whhb_hi, g_whhb_hi); cudaGetSymbolAddress((void**)&whhb_lo, g_whhb_lo);
    cudaGetSymbolAddress((void**)&h1_hi,   g_h1_hi);   cudaGetSymbolAddress((void**)&h1_lo,   g_h1_lo);
    cudaGetSymbolAddress((void**)&gnn_hi,  g_gnn_hi);  cudaGetSymbolAddress((void**)&gnn_lo,  g_gnn_lo);
    cudaGetSymbolAddress((void**)&hb_hi,   g_hb_hi);   cudaGetSymbolAddress((void**)&hb_lo,   g_hb_lo);

    static cudaStream_t s2 = nullptr;
    static cudaEvent_t evFork = nullptr, evJoin = nullptr;
    if (!s2) {
        cudaStreamCreateWithFlags(&s2, cudaStreamNonBlocking);
        cudaEventCreateWithFlags(&evFork, cudaEventDisableTiming);
        cudaEventCreateWithFlags(&evJoin, cudaEventDisableTiming);
        cudaFuncSetAttribute((const void*)wmma_gemm<0, 1>,
                             cudaFuncAttributeMaxDynamicSharedMemorySize, SMEM_BYTES);
        cudaFuncSetAttribute((const void*)wmma_gemm<1, 1>,
                             cudaFuncAttributeMaxDynamicSharedMemorySize, SMEM_BYTES);
        cudaFuncSetAttribute((const void*)wmma_gemm<1, 4>,
                             cudaFuncAttributeMaxDynamicSharedMemorySize, SMEM_BYTES);
    }

    const long NH = (long)NN * HH;
    const long XGZ = (long)NN * KK * H4;

    // --- fork: extract (DRAM-bound, independent) runs on side stream ---
    cudaEventRecord(evFork, 0);
    cudaStreamWaitEvent(s2, evFork, 0);
    extract_kernel<<<NN, 256, 0, s2>>>(adj);
    cudaEventRecord(evJoin, s2);

    // --- main stream: split + GCN layer-1 GEMM (independent of extract) ---
    split_all<<<(S_FEAT + 6 * S_W) / 256, 256>>>(feat, w1, w2, wih_f, whh_f, wih_b, whh_b);
    wmma_gemm<0, 1><<<dim3(2, NN / 128, KK), 256, SMEM_BYTES>>>(
        feat_hi, feat_lo, 0, w1_hi, w1_lo, nullptr, nullptr, (long)FF * HH, HH, dT, NH, HH);

    // --- join: spmm needs neighbor lists ---
    cudaStreamWaitEvent(0, evJoin, 0);

    spmm_kernel<<<dim3(NN / 8, KK), 256>>>(dT, b1, nullptr, h1_hi, h1_lo, HH, NH);

    // GCN layer 2
    wmma_gemm<0, 1><<<dim3(2, NN / 128, KK), 256, SMEM_BYTES>>>(
        h1_hi, h1_lo, NN, w2_hi, w2_lo, nullptr, nullptr, (long)HH * HH, HH, dT, NH, HH);
    spmm_kernel<<<dim3(NN / 8, KK), 256>>>(dT, b2, dgnn, gnn_hi, gnn_lo, (long)KK * HH, HH);

    // LSTM input precompute (both directions batched over z, A staged once per
    // 4 N-chunks = 256 output cols)
    wmma_gemm<1, 4><<<dim3(2, (NN * KK) / 128, 2), 256, SMEM_BYTES>>>(
        gnn_hi, gnn_lo, 0, wihf_hi, wihf_lo, wihb_hi, wihb_lo, 0, HH, dXG, XGZ, H4);

    // Bidirectional LSTM, 4 steps; fwd+bwd batched per step
    for (int step = 0; step < KK; step++) {
        if (step > 0)
            wmma_gemm<1, 1><<<dim3(H4 / 64, NN / 128, 2), 256, SMEM_BYTES>>>(
                hb_hi, hb_lo, NN, whhf_hi, whhf_lo, whhb_hi, whhb_lo, 0, HH,
                dHh, (long)NN * H4, H4);
        lstm_gate_kernel<<<dim3((NN * 32) / 256, 2), 256>>>(
            dXG, dHh, bih_f, bhh_f, bih_b, bhh_b, dcbuf, dhf, dhb, step);
    }

    // attention + pooling + classifier
    final_kernel<<<NN, 128>>>(rw, rb, ow, ob, out);

    (void)in_sizes; (void)n_in; (void)out_size;
}

// round 14
// speedup vs baseline: 1.1997x; 1.0318x over previous
#include <cuda_runtime.h>
#include <cuda_bf16.h>
#include <mma.h>
#include <math.h>
#include <cstdint>

using namespace nvcuda;

// Problem constants
#define NN 4096
#define FF 128
#define HH 128
#define KK 4
#define CC 10
#define H4 512
#define MAXNB 256

typedef __nv_bfloat16 bf16;

// ---------------- scratch (device globals; no runtime allocation) ----------------
__device__ float g_dinv[NN * KK];
__device__ int   g_cnt[NN * KK];
__device__ int   g_cols[(size_t)NN * KK * MAXNB];
__device__ float g_T[(size_t)KK * NN * HH];
__device__ float g_gnn[(size_t)NN * KK * HH];
__device__ float g_XG[(size_t)2 * NN * KK * H4];
__device__ float g_Hh[(size_t)2 * NN * H4];
__device__ float g_cbuf[(size_t)2 * NN * HH];
__device__ float g_hfwd[(size_t)NN * KK * HH];
__device__ float g_hbwd[(size_t)NN * KK * HH];

// pre-split bf16 hi/lo buffers
__device__ bf16 g_feat_hi[NN * FF],            g_feat_lo[NN * FF];
__device__ bf16 g_w1_hi[KK * FF * HH],         g_w1_lo[KK * FF * HH];
__device__ bf16 g_w2_hi[KK * HH * HH],         g_w2_lo[KK * HH * HH];
__device__ bf16 g_wihf_hi[H4 * HH],            g_wihf_lo[H4 * HH];
__device__ bf16 g_whhf_hi[H4 * HH],            g_whhf_lo[H4 * HH];
__device__ bf16 g_wihb_hi[H4 * HH],            g_wihb_lo[H4 * HH];
__device__ bf16 g_whhb_hi[H4 * HH],            g_whhb_lo[H4 * HH];
__device__ bf16 g_h1_hi[(size_t)KK * NN * HH], g_h1_lo[(size_t)KK * NN * HH];
__device__ bf16 g_gnn_hi[(size_t)NN * KK * HH],g_gnn_lo[(size_t)NN * KK * HH];
__device__ bf16 g_hb_hi[(size_t)2 * NN * HH],  g_hb_lo[(size_t)2 * NN * HH];

__device__ __forceinline__ uint32_t smem_u32(const void* p) {
    uint32_t a;
    asm("{ .reg .u64 t; cvta.to.shared.u64 t, %1; cvt.u32.u64 %0, t; }" : "=r"(a) : "l"(p));
    return a;
}

__device__ __forceinline__ void split1(float x, bf16* hi, bf16* lo, size_t idx) {
    bf16 h = __float2bfloat16(x);
    hi[idx] = h;
    lo[idx] = __float2bfloat16(x - __bfloat162float(h));
}

// ============================================================================
// wmma bf16 split-precision GEMM: 128x64 tiles, 256 thr, cp.async staging,
// 2 blocks/SM. (exact R8 configuration)
// BCOL=0: B is [128 x ldb] K-major, take cols bn..bn+63
// BCOL=1: B is [N x 128] row-major, used as B^T, take rows bn..bn+63
// ============================================================================
#define LDA 136
#define A_E (128 * LDA)
#define B_E 9216
#define SMEM_BYTES ((2 * A_E + 2 * B_E) * 2)

template <int BCOL>
__global__ __launch_bounds__(256, 2)
void wmma_gemm(const bf16* __restrict__ Ahi_g, const bf16* __restrict__ Alo_g,
               long a_zrows,
               const bf16* __restrict__ Bhi0, const bf16* __restrict__ Blo0,
               const bf16* __restrict__ Bhi1, const bf16* __restrict__ Blo1,
               long b_zstride, int ldb,
               float* __restrict__ C, long c_zstride, int ldc) {
    extern __shared__ bf16 sm[];
    bf16* Ahi = sm;
    bf16* Alo = sm + A_E;
    bf16* Bhi = sm + 2 * A_E;
    bf16* Blo = sm + 2 * A_E + B_E;

    int tid = threadIdx.x;
    int z = blockIdx.z;
    int bn = blockIdx.x * 64;
    long arow0 = (long)blockIdx.y * 128 + (long)z * a_zrows;
    const bf16* bhp = (Bhi1 && z) ? Bhi1 : (Bhi0 + (size_t)z * b_zstride);
    const bf16* blp = (Blo1 && z) ? Blo1 : (Blo0 + (size_t)z * b_zstride);

    uint32_t sb = smem_u32(sm);
    const bf16* asrc0 = Ahi_g + arow0 * 128;
    const bf16* asrc1 = Alo_g + arow0 * 128;
#pragma unroll
    for (int t = 0; t < 2; t++) {
        const bf16* gb = t ? asrc1 : asrc0;
        uint32_t base = sb + t * (A_E * 2);
#pragma unroll
        for (int it = 0; it < 8; it++) {
            int i = it * 256 + tid;
            int r = i >> 4, ck = i & 15;
            const char* g = (const char*)(gb + (size_t)r * 128) + ck * 16;
            uint32_t s = base + r * 272 + ck * 16;
            asm volatile("cp.async.cg.shared.global [%0], [%1], 16;" :: "r"(s), "l"(g));
        }
    }
    if (!BCOL) {
#pragma unroll
        for (int t = 0; t < 2; t++) {
            const bf16* gb = (t ? blp : bhp) + bn;
            uint32_t base = sb + (2 * A_E + t * B_E) * 2;
#pragma unroll
            for (int it = 0; it < 4; it++) {
                int i = it * 256 + tid;
                int r = i >> 3, ck = i & 7;
                const char* g = (const char*)(gb + (size_t)r * ldb) + ck * 16;
                uint32_t s = base + r * 144 + ck * 16;
                asm volatile("cp.async.cg.shared.global [%0], [%1], 16;" :: "r"(s), "l"(g));
            }
        }
    } else {
#pragma unroll
        for (int t = 0; t < 2; t++) {
            const bf16* gb = (t ? blp : bhp) + (size_t)bn * 128;
            uint32_t base = sb + (2 * A_E + t * B_E) * 2;
#pragma unroll
            for (int it = 0; it < 4; it++) {
                int i = it * 256 + tid;
                int r = i >> 4, ck = i & 15;
                const char* g = (const char*)(gb + (size_t)r * 128) + ck * 16;
                uint32_t s = base + r * 272 + ck * 16;
                asm volatile("cp.async.cg.shared.global [%0], [%1], 16;" :: "r"(s), "l"(g));
            }
        }
    }
    asm volatile("cp.async.commit_group;");
    asm volatile("cp.async.wait_group 0;");
    __syncthreads();

    int w = tid >> 5;
    int wm = (w & 3) * 32;
    int wn = (w >> 2) * 32;

    wmma::fragment<wmma::accumulator, 16, 16, 16, float> acc[2][2];
#pragma unroll
    for (int i = 0; i < 2; i++)
#pragma unroll
        for (int j = 0; j < 2; j++)
            wmma::fill_fragment(acc[i][j], 0.0f);

#pragma unroll
    for (int kk = 0; kk < 128; kk += 16) {
        wmma::fragment<wmma::matrix_a, 16, 16, 16, bf16, wmma::row_major> ah[2], al[2];
#pragma unroll
        for (int i = 0; i < 2; i++) {
            wmma::load_matrix_sync(ah[i], &Ahi[(wm + 16 * i) * LDA + kk], LDA);
            wmma::load_matrix_sync(al[i], &Alo[(wm + 16 * i) * LDA + kk], LDA);
        }
        if (!BCOL) {
            wmma::fragment<wmma::matrix_b, 16, 16, 16, bf16, wmma::row_major> bh[2], bl[2];
#pragma unroll
            for (int j = 0; j < 2; j++) {
                wmma::load_matrix_sync(bh[j], &Bhi[kk * 72 + wn + 16 * j], 72);
                wmma::load_matrix_sync(bl[j], &Blo[kk * 72 + wn + 16 * j], 72);
            }
#pragma unroll
            for (int i = 0; i < 2; i++)
#pragma unroll
                for (int j = 0; j < 2; j++) {
                    wmma::mma_sync(acc[i][j], ah[i], bh[j], acc[i][j]);
                    wmma::mma_sync(acc[i][j], ah[i], bl[j], acc[i][j]);
                    wmma::mma_sync(acc[i][j], al[i], bh[j], acc[i][j]);
                }
        } else {
            wmma::fragment<wmma::matrix_b, 16, 16, 16, bf16, wmma::col_major> bh[2], bl[2];
#pragma unroll
            for (int j = 0; j < 2; j++) {
                wmma::load_matrix_sync(bh[j], &Bhi[(wn + 16 * j) * 136 + kk], 136);
                wmma::load_matrix_sync(bl[j], &Blo[(wn + 16 * j) * 136 + kk], 136);
            }
#pragma unroll
            for (int i = 0; i < 2; i++)
#pragma unroll
                for (int j = 0; j < 2; j++) {
                    wmma::mma_sync(acc[i][j], ah[i], bh[j], acc[i][j]);
                    wmma::mma_sync(acc[i][j], ah[i], bl[j], acc[i][j]);
                    wmma::mma_sync(acc[i][j], al[i], bh[j], acc[i][j]);
                }
        }
    }

    float* Cp = C + (size_t)z * c_zstride + ((size_t)blockIdx.y * 128) * ldc + bn;
#pragma unroll
    for (int i = 0; i < 2; i++)
#pragma unroll
        for (int j = 0; j < 2; j++)
            wmma::store_matrix_sync(&Cp[(size_t)(wm + 16 * i) * ldc + wn + 16 * j],
                                    acc[i][j], ldc, wmma::mem_row_major);
}

// ---------------- one-shot split of feat + all weight matrices ----------------
#define S_FEAT (NN * FF)
#define S_W    (KK * FF * HH)
__global__ void split_all(const float* __restrict__ feat, const float* __restrict__ w1,
                          const float* __restrict__ w2,
                          const float* __restrict__ wihf, const float* __restrict__ whhf,
                          const float* __restrict__ wihb, const float* __restrict__ whhb) {
    int i = blockIdx.x * 256 + threadIdx.x;
    const float* s; bf16 *h, *l; int off;
    if      (i < S_FEAT)             { s = feat; h = g_feat_hi; l = g_feat_lo; off = 0; }
    else if (i < S_FEAT + S_W)       { s = w1;   h = g_w1_hi;   l = g_w1_lo;   off = S_FEAT; }
    else if (i < S_FEAT + 2 * S_W)   { s = w2;   h = g_w2_hi;   l = g_w2_lo;   off = S_FEAT + S_W; }
    else if (i < S_FEAT + 3 * S_W)   { s = wihf; h = g_wihf_hi; l = g_wihf_lo; off = S_FEAT + 2 * S_W; }
    else if (i < S_FEAT + 4 * S_W)   { s = whhf; h = g_whhf_hi; l = g_whhf_lo; off = S_FEAT + 3 * S_W; }
    else if (i < S_FEAT + 5 * S_W)   { s = wihb; h = g_wihb_hi; l = g_wihb_lo; off = S_FEAT + 4 * S_W; }
    else if (i < S_FEAT + 6 * S_W)   { s = whhb; h = g_whhb_hi; l = g_whhb_lo; off = S_FEAT + 5 * S_W; }
    else return;
    int j = i - off;
    split1(s[j], h, l, j);
}

// ---------------- adjacency scan: build neighbor lists + dinv ----------------
__global__ void extract_kernel(const float* __restrict__ adj) {
    int n = blockIdx.x;
    __shared__ int scnt[KK];
    if (threadIdx.x < KK) scnt[threadIdx.x] = 0;
    __syncthreads();
    const float4* row = (const float4*)(adj + (size_t)n * NN * KK);
    for (int j = threadIdx.x; j < NN; j += blockDim.x) {
        float4 v = row[j];
        if (v.x > 0.5f) { int p = atomicAdd(&scnt[0], 1); if (p < MAXNB) g_cols[((size_t)(n * KK + 0)) * MAXNB + p] = j; }
        if (v.y > 0.5f) { int p = atomicAdd(&scnt[1], 1); if (p < MAXNB) g_cols[((size_t)(n * KK + 1)) * MAXNB + p] = j; }
        if (v.z > 0.5f) { int p = atomicAdd(&scnt[2], 1); if (p < MAXNB) g_cols[((size_t)(n * KK + 2)) * MAXNB + p] = j; }
        if (v.w > 0.5f) { int p = atomicAdd(&scnt[3], 1); if (p < MAXNB) g_cols[((size_t)(n * KK + 3)) * MAXNB + p] = j; }
    }
    __syncthreads();
    if (threadIdx.x < KK) {
        int m = scnt[threadIdx.x];
        if (m > MAXNB) m = MAXNB;
        g_cnt[n * KK + threadIdx.x] = m;
        g_dinv[n * KK + threadIdx.x] = rsqrtf((float)m + 1.0f);
    }
}

// ---------------- SpMM: warp per (n,k), destaged (no smem) ----------------
// Per 8-batch: lanes 0-7 load cols + dinv; shfl broadcast; 8 float4 gathers.
// Staging latency pipelines with the gather stream.
__global__ __launch_bounds__(256)
void spmm_kernel(const float* __restrict__ x, const float* __restrict__ bias,
                 float* __restrict__ out32,
                 bf16* __restrict__ ohi, bf16* __restrict__ olo,
                 long os_n, long os_k) {
    int w = threadIdx.x >> 5, lane = threadIdx.x & 31;
    int n = blockIdx.x * 8 + w;
    int k = blockIdx.y;
    int m = g_cnt[n * KK + k];
    float dn = g_dinv[n * KK + k];
    const int* cl = &g_cols[((size_t)(n * KK + k)) * MAXNB];
    const float* xk = x + (size_t)k * NN * HH;
    int c4 = lane * 4;
    float4 xs = *(const float4*)(xk + (size_t)n * HH + c4);
    float4 acc = make_float4(dn * xs.x, dn * xs.y, dn * xs.z, dn * xs.w);
    int i = 0;
    for (; i + 8 <= m; i += 8) {
        int jj = 0; float wj = 0.0f;
        if (lane < 8) {
            jj = cl[i + lane];
            wj = g_dinv[jj * KK + k];
        }
        float4 v[8]; float wv[8];
#pragma unroll
        for (int u = 0; u < 8; u++) {
            int j = __shfl_sync(0xffffffffu, jj, u);
            wv[u] = __shfl_sync(0xffffffffu, wj, u);
            v[u] = *(const float4*)(xk + (size_t)j * HH + c4);
        }
#pragma unroll
        for (int u = 0; u < 8; u++) {
            acc.x += wv[u] * v[u].x; acc.y += wv[u] * v[u].y;
            acc.z += wv[u] * v[u].z; acc.w += wv[u] * v[u].w;
        }
    }
    for (; i < m; i++) {
        int j = cl[i];
        float wj = g_dinv[j * KK + k];
        float4 v = *(const float4*)(xk + (size_t)j * HH + c4);
        acc.x += wj * v.x; acc.y += wj * v.y; acc.z += wj * v.z; acc.w += wj * v.w;
    }
    float4 bv = *(const float4*)(bias + k * HH + c4);
    float4 r = make_float4(dn * acc.x + bv.x, dn * acc.y + bv.y,
                           dn * acc.z + bv.z, dn * acc.w + bv.w);
    size_t idx = (size_t)n * os_n + (size_t)k * os_k + c4;
    if (out32) *(float4*)(out32 + idx) = r;
    bf16 h0 = __float2bfloat16(r.x), h1 = __float2bfloat16(r.y);
    bf16 h2 = __float2bfloat16(r.z), h3 = __float2bfloat16(r.w);
    *(__nv_bfloat162*)(ohi + idx)     = __halves2bfloat162(h0, h1);
    *(__nv_bfloat162*)(ohi + idx + 2) = __halves2bfloat162(h2, h3);
    *(__nv_bfloat162*)(olo + idx)     = __halves2bfloat162(
        __float2bfloat16(r.x - __bfloat162float(h0)), __float2bfloat16(r.y - __bfloat162float(h1)));
    *(__nv_bfloat162*)(olo + idx + 2) = __halves2bfloat162(
        __float2bfloat16(r.z - __bfloat162float(h2)), __float2bfloat16(r.w - __bfloat162float(h3)));
}

// ---------------- LSTM gate fusion, float4, both dirs batched (blockIdx.y = dir) ----------------
__global__ __launch_bounds__(256)
void lstm_gate_kernel(const float* __restrict__ XG, const float* __restrict__ Hh,
                      const float* __restrict__ bi_f, const float* __restrict__ bh_f,
                      const float* __restrict__ bi_b, const float* __restrict__ bh_b,
                      float* __restrict__ cbuf,
                      float* __restrict__ hf, float* __restrict__ hb, int step) {
    int dir = blockIdx.y;
    int idx = blockIdx.x * 256 + threadIdx.x;   // 0 .. NN*32-1
    int n = idx >> 5, q = (idx & 31) * 4;
    int t = dir ? (KK - 1 - step) : step;
    int first = (step == 0);
    const float* xg = XG + (size_t)dir * NN * KK * H4 + ((size_t)n * KK + t) * H4;
    const float* bi = dir ? bi_b : bi_f;
    const float* bh = dir ? bh_b : bh_f;
    float4 vi = *(const float4*)(xg + q);
    float4 vf = *(const float4*)(xg + HH + q);
    float4 vg = *(const float4*)(xg + 2 * HH + q);
    float4 vo = *(const float4*)(xg + 3 * HH + q);
    float4 b0 = *(const float4*)(bi + q),          c0 = *(const float4*)(bh + q);
    float4 b1 = *(const float4*)(bi + HH + q),     c1 = *(const float4*)(bh + HH + q);
    float4 b2 = *(const float4*)(bi + 2 * HH + q), c2 = *(const float4*)(bh + 2 * HH + q);
    float4 b3 = *(const float4*)(bi + 3 * HH + q), c3 = *(const float4*)(bh + 3 * HH + q);
    vi.x += b0.x + c0.x; vi.y += b0.y + c0.y; vi.z += b0.z + c0.z; vi.w += b0.w + c0.w;
    vf.x += b1.x + c1.x; vf.y += b1.y + c1.y; vf.z += b1.z + c1.z; vf.w += b1.w + c1.w;
    vg.x += b2.x + c2.x; vg.y += b2.y + c2.y; vg.z += b2.z + c2.z; vg.w += b2.w + c2.w;
    vo.x += b3.x + c3.x; vo.y += b3.y + c3.y; vo.z += b3.z + c3.z; vo.w += b3.w + c3.w;
    if (!first) {
        const float* hh = Hh + (size_t)dir * NN * H4 + (size_t)n * H4;
        float4 h0 = *(const float4*)(hh + q);
        float4 h1 = *(const float4*)(hh + HH + q);
        float4 h2 = *(const float4*)(hh + 2 * HH + q);
        float4 h3 = *(const float4*)(hh + 3 * HH + q);
        vi.x += h0.x; vi.y += h0.y; vi.z += h0.z; vi.w += h0.w;
        vf.x += h1.x; vf.y += h1.y; vf.z += h1.z; vf.w += h1.w;
        vg.x += h2.x; vg.y += h2.y; vg.z += h2.z; vg.w += h2.w;
        vo.x += h3.x; vo.y += h3.y; vo.z += h3.z; vo.w += h3.w;
    }
    size_t sidx = (size_t)dir * NN * HH + (size_t)n * HH + q;
    float4 cprev = first ? make_float4(0.f, 0.f, 0.f, 0.f) : *(const float4*)(cbuf + sidx);
    float4 cnew, hv;
#define GATE_COMP(E) { \
    float I = 1.0f / (1.0f + expf(-vi.E)); \
    float Fv = 1.0f / (1.0f + expf(-vf.E)); \
    float G = tanhf(vg.E); \
    float O = 1.0f / (1.0f + expf(-vo.E)); \
    float cn = Fv * cprev.E + I * G; \
    cnew.E = cn; hv.E = O * tanhf(cn); }
    GATE_COMP(x) GATE_COMP(y) GATE_COMP(z) GATE_COMP(w)
#undef GATE_COMP
    *(float4*)(cbuf + sidx) = cnew;
    bf16 h0 = __float2bfloat16(hv.x), h1 = __float2bfloat16(hv.y);
    bf16 h2 = __float2bfloat16(hv.z), h3 = __float2bfloat16(hv.w);
    *(__nv_bfloat162*)(g_hb_hi + sidx)     = __halves2bfloat162(h0, h1);
    *(__nv_bfloat162*)(g_hb_hi + sidx + 2) = __halves2bfloat162(h2, h3);
    *(__nv_bfloat162*)(g_hb_lo + sidx)     = __halves2bfloat162(
        __float2bfloat16(hv.x - __bfloat162float(h0)), __float2bfloat16(hv.y - __bfloat162float(h1)));
    *(__nv_bfloat162*)(g_hb_lo + sidx + 2) = __halves2bfloat162(
        __float2bfloat16(hv.z - __bfloat162float(h2)), __float2bfloat16(hv.w - __bfloat162float(h3)));
    float* hout = dir ? hb : hf;
    *(float4*)(hout + ((size_t)n * KK + t) * HH + q) = hv;
}

// ---------------- attention + pooling + classifier + softmax ----------------
__global__ void final_kernel(const float* __restrict__ rw, const float* __restrict__ rb,
                             const float* __restrict__ ow, const float* __restrict__ ob,
                             float* __restrict__ out) {
    int n = blockIdx.x;
    int t = threadIdx.x;
    __shared__ float red[4];
    __shared__ float sattn[KK];
    __shared__ float sp[HH];
    __shared__ float sl[16];

    for (int k = 0; k < KK; k++) {
        float p = g_hfwd[((size_t)n * KK + k) * HH + t] * rw[t]
                + g_hbwd[((size_t)n * KK + k) * HH + t] * rw[HH + t];
        for (int o = 16; o; o >>= 1) p += __shfl_down_sync(0xffffffffu, p, o);
        if ((t & 31) == 0) red[t >> 5] = p;
        __syncthreads();
        if (t == 0) sattn[k] = red[0] + red[1] + red[2] + red[3] + rb[0];
        __syncthreads();
    }
    if (t == 0) {
        float m = sattn[0];
        for (int k = 1; k < KK; k++) m = fmaxf(m, sattn[k]);
        float s = 0.0f;
        for (int k = 0; k < KK; k++) { sattn[k] = expf(sattn[k] - m); s += sattn[k]; }
        float inv = 1.0f / s;
        for (int k = 0; k < KK; k++) sattn[k] *= inv;
    }
    __syncthreads();
    float pooled = 0.0f;
    for (int k = 0; k < KK; k++)
        pooled += sattn[k] * g_gnn[((size_t)n * KK + k) * HH + t];
    sp[t] = pooled;
    __syncthreads();
    int w = t >> 5, lane = t & 31;
    for (int c = w; c < CC; c += 4) {
        float s = sp[lane] * ow[c * HH + lane]
                + sp[lane + 32] * ow[c * HH + lane + 32]
                + sp[lane + 64] * ow[c * HH + lane + 64]
                + sp[lane + 96] * ow[c * HH + lane + 96];
        for (int o = 16; o; o >>= 1) s += __shfl_down_sync(0xffffffffu, s, o);
        if (lane == 0) sl[c] = s + ob[c];
    }
    __syncthreads();
    if (t == 0) {
        float m = sl[0];
        for (int c = 1; c < CC; c++) m = fmaxf(m, sl[c]);
        float s = 0.0f;
        for (int c = 0; c < CC; c++) { sl[c] = expf(sl[c] - m); s += sl[c]; }
        float inv = 1.0f / s;
        for (int c = 0; c < CC; c++) out[(size_t)n * CC + c] = sl[c] * inv;
    }
}

// ---------------- host orchestration ----------------
extern "C" void kernel_launch(void* const* d_in, const int* in_sizes, int n_in,
                              void* d_out, int out_size) {
    const float* feat  = (const float*)d_in[0];
    const float* adj   = (const float*)d_in[1];
    const float* w1    = (const float*)d_in[2];
    const float* b1    = (const float*)d_in[3];
    const float* w2    = (const float*)d_in[4];
    const float* b2    = (const float*)d_in[5];
    const float* wih_f = (const float*)d_in[6];
    const float* whh_f = (const float*)d_in[7];
    const float* bih_f = (const float*)d_in[8];
    const float* bhh_f = (const float*)d_in[9];
    const float* wih_b = (const float*)d_in[10];
    const float* whh_b = (const float*)d_in[11];
    const float* bih_b = (const float*)d_in[12];
    const float* bhh_b = (const float*)d_in[13];
    const float* rw    = (const float*)d_in[14];
    const float* rb    = (const float*)d_in[15];
    const float* ow    = (const float*)d_in[16];
    const float* ob    = (const float*)d_in[17];
    float* out = (float*)d_out;

    float *dT, *dgnn, *dXG, *dHh, *dcbuf, *dhf, *dhb;
    cudaGetSymbolAddress((void**)&dT,    g_T);
    cudaGetSymbolAddress((void**)&dgnn,  g_gnn);
    cudaGetSymbolAddress((void**)&dXG,   g_XG);
    cudaGetSymbolAddress((void**)&dHh,   g_Hh);
    cudaGetSymbolAddress((void**)&dcbuf, g_cbuf);
    cudaGetSymbolAddress((void**)&dhf,   g_hfwd);
    cudaGetSymbolAddress((void**)&dhb,   g_hbwd);

    bf16 *feat_hi, *feat_lo, *w1_hi, *w1_lo, *w2_hi, *w2_lo;
    bf16 *wihf_hi, *wihf_lo, *whhf_hi, *whhf_lo, *wihb_hi, *wihb_lo, *whhb_hi, *whhb_lo;
    bf16 *h1_hi, *h1_lo, *gnn_hi, *gnn_lo, *hb_hi, *hb_lo;
    cudaGetSymbolAddress((void**)&feat_hi, g_feat_hi); cudaGetSymbolAddress((void**)&feat_lo, g_feat_lo);
    cudaGetSymbolAddress((void**)&w1_hi,   g_w1_hi);   cudaGetSymbolAddress((void**)&w1_lo,   g_w1_lo);
    cudaGetSymbolAddress((void**)&w2_hi,   g_w2_hi);   cudaGetSymbolAddress((void**)&w2_lo,   g_w2_lo);
    cudaGetSymbolAddress((void**)&wihf_hi, g_wihf_hi); cudaGetSymbolAddress((void**)&wihf_lo, g_wihf_lo);
    cudaGetSymbolAddress((void**)&whhf_hi, g_whhf_hi); cudaGetSymbolAddress((void**)&whhf_lo, g_whhf_lo);
    cudaGetSymbolAddress((void**)&wihb_hi, g_wihb_hi); cudaGetSymbolAddress((void**)&wihb_lo, g_wihb_lo);
    cudaGetSymbolAddress((void**)&whhb_hi, g_whhb_hi); cudaGetSymbolAddress((void**)&whhb_lo, g_whhb_lo);
    cudaGetSymbolAddress((void**)&h1_hi,   g_h1_hi);   cudaGetSymbolAddress((void**)&h1_lo,   g_h1_lo);
    cudaGetSymbolAddress((void**)&gnn_hi,  g_gnn_hi);  cudaGetSymbolAddress((void**)&gnn_lo,  g_gnn_lo);
    cudaGetSymbolAddress((void**)&hb_hi,   g_hb_hi);   cudaGetSymbolAddress((void**)&hb_lo,   g_hb_lo);

    static cudaStream_t s2 = nullptr;
    static cudaEvent_t evFork = nullptr, evJoin = nullptr;
    if (!s2) {
        cudaStreamCreateWithFlags(&s2, cudaStreamNonBlocking);
        cudaEventCreateWithFlags(&evFork, cudaEventDisableTiming);
        cudaEventCreateWithFlags(&evJoin, cudaEventDisableTiming);
        cudaFuncSetAttribute((const void*)wmma_gemm<0>,
                             cudaFuncAttributeMaxDynamicSharedMemorySize, SMEM_BYTES);
        cudaFuncSetAttribute((const void*)wmma_gemm<1>,
                             cudaFuncAttributeMaxDynamicSharedMemorySize, SMEM_BYTES);
    }

    const long NH = (long)NN * HH;
    const long XGZ = (long)NN * KK * H4;

    // --- fork: extract (DRAM-bound, independent) runs on side stream ---
    cudaEventRecord(evFork, 0);
    cudaStreamWaitEvent(s2, evFork, 0);
    extract_kernel<<<NN, 256, 0, s2>>>(adj);
    cudaEventRecord(evJoin, s2);

    // --- main stream: split + GCN layer-1 GEMM (independent of extract) ---
    split_all<<<(S_FEAT + 6 * S_W) / 256, 256>>>(feat, w1, w2, wih_f, whh_f, wih_b, whh_b);
    wmma_gemm<0><<<dim3(2, NN / 128, KK), 256, SMEM_BYTES>>>(
        feat_hi, feat_lo, 0, w1_hi, w1_lo, nullptr, nullptr, (long)FF * HH, HH, dT, NH, HH);

    // --- join: spmm needs neighbor lists ---
    cudaStreamWaitEvent(0, evJoin, 0);

    spmm_kernel<<<dim3(NN / 8, KK), 256>>>(dT, b1, nullptr, h1_hi, h1_lo, HH, NH);

    // GCN layer 2
    wmma_gemm<0><<<dim3(2, NN / 128, KK), 256, SMEM_BYTES>>>(
        h1_hi, h1_lo, NN, w2_hi, w2_lo, nullptr, nullptr, (long)HH * HH, HH, dT, NH, HH);
    spmm_kernel<<<dim3(NN / 8, KK), 256>>>(dT, b2, dgnn, gnn_hi, gnn_lo, (long)KK * HH, HH);

    // LSTM input precompute (both directions batched over z)
    wmma_gemm<1><<<dim3(H4 / 64, (NN * KK) / 128, 2), 256, SMEM_BYTES>>>(
        gnn_hi, gnn_lo, 0, wihf_hi, wihf_lo, wihb_hi, wihb_lo, 0, HH, dXG, XGZ, H4);

    // Bidirectional LSTM, 4 steps; fwd+bwd batched per step
    for (int step = 0; step < KK; step++) {
        if (step > 0)
            wmma_gemm<1><<<dim3(H4 / 64, NN / 128, 2), 256, SMEM_BYTES>>>(
                hb_hi, hb_lo, NN, whhf_hi, whhf_lo, whhb_hi, whhb_lo, 0, HH,
                dHh, (long)NN * H4, H4);
        lstm_gate_kernel<<<dim3((NN * 32) / 256, 2), 256>>>(
            dXG, dHh, bih_f, bhh_f, bih_b, bhh_b, dcbuf, dhf, dhb, step);
    }

    // attention + pooling + classifier
    final_kernel<<<NN, 128>>>(rw, rb, ow, ob, out);

    (void)in_sizes; (void)n_in; (void)out_size;
}

// round 15
// speedup vs baseline: 1.2167x; 1.0142x over previous
#include <cuda_runtime.h>
#include <cuda_bf16.h>
#include <mma.h>
#include <math.h>
#include <cstdint>

using namespace nvcuda;

// Problem constants
#define NN 4096
#define FF 128
#define HH 128
#define KK 4
#define CC 10
#define H4 512
#define MAXNB 256

typedef __nv_bfloat16 bf16;

// ---------------- scratch (device globals; no runtime allocation) ----------------
__device__ float g_dinv[NN * KK];
__device__ int   g_cnt[NN * KK];
__device__ int   g_cols[(size_t)NN * KK * MAXNB];
__device__ int2  g_colw[(size_t)NN * KK * MAXNB];   // packed (col, weight-bits)
__device__ float g_T[(size_t)KK * NN * HH];
__device__ float g_gnn[(size_t)NN * KK * HH];
__device__ float g_XG[(size_t)2 * NN * KK * H4];
__device__ float g_Hh[(size_t)2 * NN * H4];
__device__ float g_cbuf[(size_t)2 * NN * HH];
__device__ float g_hfwd[(size_t)NN * KK * HH];
__device__ float g_hbwd[(size_t)NN * KK * HH];

// pre-split bf16 hi/lo buffers
__device__ bf16 g_feat_hi[NN * FF],            g_feat_lo[NN * FF];
__device__ bf16 g_w1_hi[KK * FF * HH],         g_w1_lo[KK * FF * HH];
__device__ bf16 g_w2_hi[KK * HH * HH],         g_w2_lo[KK * HH * HH];
__device__ bf16 g_wihf_hi[H4 * HH],            g_wihf_lo[H4 * HH];
__device__ bf16 g_whhf_hi[H4 * HH],            g_whhf_lo[H4 * HH];
__device__ bf16 g_wihb_hi[H4 * HH],            g_wihb_lo[H4 * HH];
__device__ bf16 g_whhb_hi[H4 * HH],            g_whhb_lo[H4 * HH];
__device__ bf16 g_h1_hi[(size_t)KK * NN * HH], g_h1_lo[(size_t)KK * NN * HH];
__device__ bf16 g_gnn_hi[(size_t)NN * KK * HH],g_gnn_lo[(size_t)NN * KK * HH];
__device__ bf16 g_hb_hi[(size_t)2 * NN * HH],  g_hb_lo[(size_t)2 * NN * HH];

__device__ __forceinline__ uint32_t smem_u32(const void* p) {
    uint32_t a;
    asm("{ .reg .u64 t; cvta.to.shared.u64 t, %1; cvt.u32.u64 %0, t; }" : "=r"(a) : "l"(p));
    return a;
}

__device__ __forceinline__ void split1(float x, bf16* hi, bf16* lo, size_t idx) {
    bf16 h = __float2bfloat16(x);
    hi[idx] = h;
    lo[idx] = __float2bfloat16(x - __bfloat162float(h));
}

// ============================================================================
// wmma bf16 split-precision GEMM: 128x64 tiles, 256 thr, cp.async staging,
// 2 blocks/SM. (exact R8/R14 configuration)
// ============================================================================
#define LDA 136
#define A_E (128 * LDA)
#define B_E 9216
#define SMEM_BYTES ((2 * A_E + 2 * B_E) * 2)

template <int BCOL>
__global__ __launch_bounds__(256, 2)
void wmma_gemm(const bf16* __restrict__ Ahi_g, const bf16* __restrict__ Alo_g,
               long a_zrows,
               const bf16* __restrict__ Bhi0, const bf16* __restrict__ Blo0,
               const bf16* __restrict__ Bhi1, const bf16* __restrict__ Blo1,
               long b_zstride, int ldb,
               float* __restrict__ C, long c_zstride, int ldc) {
    extern __shared__ bf16 sm[];
    bf16* Ahi = sm;
    bf16* Alo = sm + A_E;
    bf16* Bhi = sm + 2 * A_E;
    bf16* Blo = sm + 2 * A_E + B_E;

    int tid = threadIdx.x;
    int z = blockIdx.z;
    int bn = blockIdx.x * 64;
    long arow0 = (long)blockIdx.y * 128 + (long)z * a_zrows;
    const bf16* bhp = (Bhi1 && z) ? Bhi1 : (Bhi0 + (size_t)z * b_zstride);
    const bf16* blp = (Blo1 && z) ? Blo1 : (Blo0 + (size_t)z * b_zstride);

    uint32_t sb = smem_u32(sm);
    const bf16* asrc0 = Ahi_g + arow0 * 128;
    const bf16* asrc1 = Alo_g + arow0 * 128;
#pragma unroll
    for (int t = 0; t < 2; t++) {
        const bf16* gb = t ? asrc1 : asrc0;
        uint32_t base = sb + t * (A_E * 2);
#pragma unroll
        for (int it = 0; it < 8; it++) {
            int i = it * 256 + tid;
            int r = i >> 4, ck = i & 15;
            const char* g = (const char*)(gb + (size_t)r * 128) + ck * 16;
            uint32_t s = base + r * 272 + ck * 16;
            asm volatile("cp.async.cg.shared.global [%0], [%1], 16;" :: "r"(s), "l"(g));
        }
    }
    if (!BCOL) {
#pragma unroll
        for (int t = 0; t < 2; t++) {
            const bf16* gb = (t ? blp : bhp) + bn;
            uint32_t base = sb + (2 * A_E + t * B_E) * 2;
#pragma unroll
            for (int it = 0; it < 4; it++) {
                int i = it * 256 + tid;
                int r = i >> 3, ck = i & 7;
                const char* g = (const char*)(gb + (size_t)r * ldb) + ck * 16;
                uint32_t s = base + r * 144 + ck * 16;
                asm volatile("cp.async.cg.shared.global [%0], [%1], 16;" :: "r"(s), "l"(g));
            }
        }
    } else {
#pragma unroll
        for (int t = 0; t < 2; t++) {
            const bf16* gb = (t ? blp : bhp) + (size_t)bn * 128;
            uint32_t base = sb + (2 * A_E + t * B_E) * 2;
#pragma unroll
            for (int it = 0; it < 4; it++) {
                int i = it * 256 + tid;
                int r = i >> 4, ck = i & 15;
                const char* g = (const char*)(gb + (size_t)r * 128) + ck * 16;
                uint32_t s = base + r * 272 + ck * 16;
                asm volatile("cp.async.cg.shared.global [%0], [%1], 16;" :: "r"(s), "l"(g));
            }
        }
    }
    asm volatile("cp.async.commit_group;");
    asm volatile("cp.async.wait_group 0;");
    __syncthreads();

    int w = tid >> 5;
    int wm = (w & 3) * 32;
    int wn = (w >> 2) * 32;

    wmma::fragment<wmma::accumulator, 16, 16, 16, float> acc[2][2];
#pragma unroll
    for (int i = 0; i < 2; i++)
#pragma unroll
        for (int j = 0; j < 2; j++)
            wmma::fill_fragment(acc[i][j], 0.0f);

#pragma unroll
    for (int kk = 0; kk < 128; kk += 16) {
        wmma::fragment<wmma::matrix_a, 16, 16, 16, bf16, wmma::row_major> ah[2], al[2];
#pragma unroll
        for (int i = 0; i < 2; i++) {
            wmma::load_matrix_sync(ah[i], &Ahi[(wm + 16 * i) * LDA + kk], LDA);
            wmma::load_matrix_sync(al[i], &Alo[(wm + 16 * i) * LDA + kk], LDA);
        }
        if (!BCOL) {
            wmma::fragment<wmma::matrix_b, 16, 16, 16, bf16, wmma::row_major> bh[2], bl[2];
#pragma unroll
            for (int j = 0; j < 2; j++) {
                wmma::load_matrix_sync(bh[j], &Bhi[kk * 72 + wn + 16 * j], 72);
                wmma::load_matrix_sync(bl[j], &Blo[kk * 72 + wn + 16 * j], 72);
            }
#pragma unroll
            for (int i = 0; i < 2; i++)
#pragma unroll
                for (int j = 0; j < 2; j++) {
                    wmma::mma_sync(acc[i][j], ah[i], bh[j], acc[i][j]);
                    wmma::mma_sync(acc[i][j], ah[i], bl[j], acc[i][j]);
                    wmma::mma_sync(acc[i][j], al[i], bh[j], acc[i][j]);
                }
        } else {
            wmma::fragment<wmma::matrix_b, 16, 16, 16, bf16, wmma::col_major> bh[2], bl[2];
#pragma unroll
            for (int j = 0; j < 2; j++) {
                wmma::load_matrix_sync(bh[j], &Bhi[(wn + 16 * j) * 136 + kk], 136);
                wmma::load_matrix_sync(bl[j], &Blo[(wn + 16 * j) * 136 + kk], 136);
            }
#pragma unroll
            for (int i = 0; i < 2; i++)
#pragma unroll
                for (int j = 0; j < 2; j++) {
                    wmma::mma_sync(acc[i][j], ah[i], bh[j], acc[i][j]);
                    wmma::mma_sync(acc[i][j], ah[i], bl[j], acc[i][j]);
                    wmma::mma_sync(acc[i][j], al[i], bh[j], acc[i][j]);
                }
        }
    }

    float* Cp = C + (size_t)z * c_zstride + ((size_t)blockIdx.y * 128) * ldc + bn;
#pragma unroll
    for (int i = 0; i < 2; i++)
#pragma unroll
        for (int j = 0; j < 2; j++)
            wmma::store_matrix_sync(&Cp[(size_t)(wm + 16 * i) * ldc + wn + 16 * j],
                                    acc[i][j], ldc, wmma::mem_row_major);
}

// ---------------- one-shot split of feat + all weight matrices ----------------
#define S_FEAT (NN * FF)
#define S_W    (KK * FF * HH)
__global__ void split_all(const float* __restrict__ feat, const float* __restrict__ w1,
                          const float* __restrict__ w2,
                          const float* __restrict__ wihf, const float* __restrict__ whhf,
                          const float* __restrict__ wihb, const float* __restrict__ whhb) {
    int i = blockIdx.x * 256 + threadIdx.x;
    const float* s; bf16 *h, *l; int off;
    if      (i < S_FEAT)             { s = feat; h = g_feat_hi; l = g_feat_lo; off = 0; }
    else if (i < S_FEAT + S_W)       { s = w1;   h = g_w1_hi;   l = g_w1_lo;   off = S_FEAT; }
    else if (i < S_FEAT + 2 * S_W)   { s = w2;   h = g_w2_hi;   l = g_w2_lo;   off = S_FEAT + S_W; }
    else if (i < S_FEAT + 3 * S_W)   { s = wihf; h = g_wihf_hi; l = g_wihf_lo; off = S_FEAT + 2 * S_W; }
    else if (i < S_FEAT + 4 * S_W)   { s = whhf; h = g_whhf_hi; l = g_whhf_lo; off = S_FEAT + 3 * S_W; }
    else if (i < S_FEAT + 5 * S_W)   { s = wihb; h = g_wihb_hi; l = g_wihb_lo; off = S_FEAT + 4 * S_W; }
    else if (i < S_FEAT + 6 * S_W)   { s = whhb; h = g_whhb_hi; l = g_whhb_lo; off = S_FEAT + 5 * S_W; }
    else return;
    int j = i - off;
    split1(s[j], h, l, j);
}

// ---------------- adjacency scan: build neighbor lists + dinv ----------------
__global__ void extract_kernel(const float* __restrict__ adj) {
    int n = blockIdx.x;
    __shared__ int scnt[KK];
    if (threadIdx.x < KK) scnt[threadIdx.x] = 0;
    __syncthreads();
    const float4* row = (const float4*)(adj + (size_t)n * NN * KK);
    for (int j = threadIdx.x; j < NN; j += blockDim.x) {
        float4 v = row[j];
        if (v.x > 0.5f) { int p = atomicAdd(&scnt[0], 1); if (p < MAXNB) g_cols[((size_t)(n * KK + 0)) * MAXNB + p] = j; }
        if (v.y > 0.5f) { int p = atomicAdd(&scnt[1], 1); if (p < MAXNB) g_cols[((size_t)(n * KK + 1)) * MAXNB + p] = j; }
        if (v.z > 0.5f) { int p = atomicAdd(&scnt[2], 1); if (p < MAXNB) g_cols[((size_t)(n * KK + 2)) * MAXNB + p] = j; }
        if (v.w > 0.5f) { int p = atomicAdd(&scnt[3], 1); if (p < MAXNB) g_cols[((size_t)(n * KK + 3)) * MAXNB + p] = j; }
    }
    __syncthreads();
    if (threadIdx.x < KK) {
        int m = scnt[threadIdx.x];
        if (m > MAXNB) m = MAXNB;
        g_cnt[n * KK + threadIdx.x] = m;
        g_dinv[n * KK + threadIdx.x] = rsqrtf((float)m + 1.0f);
    }
}

// ---------------- pack (col, weight) pairs: one warp per (n,k) ----------------
__global__ __launch_bounds__(256)
void pack_kernel() {
    int w = threadIdx.x >> 5, lane = threadIdx.x & 31;
    int n = blockIdx.x * 8 + w;
    int k = blockIdx.y;
    int m = g_cnt[n * KK + k];
    const int* cl = &g_cols[((size_t)(n * KK + k)) * MAXNB];
    int2* cw = &g_colw[((size_t)(n * KK + k)) * MAXNB];
    for (int i = lane; i < m; i += 32) {
        int j = cl[i];
        float wj = g_dinv[j * KK + k];
        cw[i] = make_int2(j, __float_as_int(wj));
    }
}

// ---------------- SpMM: warp per (n,k), packed pairs + depth-1 pipeline ------
// Per 8-batch: lanes 0-7 hold the batch's (col, w) pair; broadcast via shfl;
// NEXT batch's pair-load issues before this batch's feature gathers.
__global__ __launch_bounds__(256)
void spmm_kernel(const float* __restrict__ x, const float* __restrict__ bias,
                 float* __restrict__ out32,
                 bf16* __restrict__ ohi, bf16* __restrict__ olo,
                 long os_n, long os_k) {
    int w = threadIdx.x >> 5, lane = threadIdx.x & 31;
    int n = blockIdx.x * 8 + w;
    int k = blockIdx.y;
    int m = g_cnt[n * KK + k];
    float dn = g_dinv[n * KK + k];
    const int2* cw = &g_colw[((size_t)(n * KK + k)) * MAXNB];
    const float* xk = x + (size_t)k * NN * HH;
    int c4 = lane * 4;
    float4 xs = *(const float4*)(xk + (size_t)n * HH + c4);
    float4 acc = make_float4(dn * xs.x, dn * xs.y, dn * xs.z, dn * xs.w);

    int2 pr = make_int2(0, 0);
    if (lane < 8 && lane < m) pr = cw[lane];
    int i = 0;
    for (; i + 8 <= m; i += 8) {
        // broadcast current batch
        int js[8]; float ws[8];
#pragma unroll
        for (int u = 0; u < 8; u++) {
            js[u] = __shfl_sync(0xffffffffu, pr.x, u);
            ws[u] = __int_as_float(__shfl_sync(0xffffffffu, pr.y, u));
        }
        // prefetch next batch pairs (overlaps with gathers below)
        int inext = i + 8;
        int2 nx = make_int2(0, 0);
        if (lane < 8 && inext + lane < m) nx = cw[inext + lane];
        // feature gathers
        float4 v[8];
#pragma unroll
        for (int u = 0; u < 8; u++)
            v[u] = *(const float4*)(xk + (size_t)js[u] * HH + c4);
#pragma unroll
        for (int u = 0; u < 8; u++) {
            acc.x += ws[u] * v[u].x; acc.y += ws[u] * v[u].y;
            acc.z += ws[u] * v[u].z; acc.w += ws[u] * v[u].w;
        }
        pr = nx;
    }
    for (; i < m; i++) {
        int2 p = cw[i];
        float wj = __int_as_float(p.y);
        float4 v = *(const float4*)(xk + (size_t)p.x * HH + c4);
        acc.x += wj * v.x; acc.y += wj * v.y; acc.z += wj * v.z; acc.w += wj * v.w;
    }
    float4 bv = *(const float4*)(bias + k * HH + c4);
    float4 r = make_float4(dn * acc.x + bv.x, dn * acc.y + bv.y,
                           dn * acc.z + bv.z, dn * acc.w + bv.w);
    size_t idx = (size_t)n * os_n + (size_t)k * os_k + c4;
    if (out32) *(float4*)(out32 + idx) = r;
    bf16 h0 = __float2bfloat16(r.x), h1 = __float2bfloat16(r.y);
    bf16 h2 = __float2bfloat16(r.z), h3 = __float2bfloat16(r.w);
    *(__nv_bfloat162*)(ohi + idx)     = __halves2bfloat162(h0, h1);
    *(__nv_bfloat162*)(ohi + idx + 2) = __halves2bfloat162(h2, h3);
    *(__nv_bfloat162*)(olo + idx)     = __halves2bfloat162(
        __float2bfloat16(r.x - __bfloat162float(h0)), __float2bfloat16(r.y - __bfloat162float(h1)));
    *(__nv_bfloat162*)(olo + idx + 2) = __halves2bfloat162(
        __float2bfloat16(r.z - __bfloat162float(h2)), __float2bfloat16(r.w - __bfloat162float(h3)));
}

// ---------------- LSTM gate fusion, float4, both dirs batched (blockIdx.y = dir) ----------------
__global__ __launch_bounds__(256)
void lstm_gate_kernel(const float* __restrict__ XG, const float* __restrict__ Hh,
                      const float* __restrict__ bi_f, const float* __restrict__ bh_f,
                      const float* __restrict__ bi_b, const float* __restrict__ bh_b,
                      float* __restrict__ cbuf,
                      float* __restrict__ hf, float* __restrict__ hb, int step) {
    int dir = blockIdx.y;
    int idx = blockIdx.x * 256 + threadIdx.x;   // 0 .. NN*32-1
    int n = idx >> 5, q = (idx & 31) * 4;
    int t = dir ? (KK - 1 - step) : step;
    int first = (step == 0);
    const float* xg = XG + (size_t)dir * NN * KK * H4 + ((size_t)n * KK + t) * H4;
    const float* bi = dir ? bi_b : bi_f;
    const float* bh = dir ? bh_b : bh_f;
    float4 vi = *(const float4*)(xg + q);
    float4 vf = *(const float4*)(xg + HH + q);
    float4 vg = *(const float4*)(xg + 2 * HH + q);
    float4 vo = *(const float4*)(xg + 3 * HH + q);
    float4 b0 = *(const float4*)(bi + q),          c0 = *(const float4*)(bh + q);
    float4 b1 = *(const float4*)(bi + HH + q),     c1 = *(const float4*)(bh + HH + q);
    float4 b2 = *(const float4*)(bi + 2 * HH + q), c2 = *(const float4*)(bh + 2 * HH + q);
    float4 b3 = *(const float4*)(bi + 3 * HH + q), c3 = *(const float4*)(bh + 3 * HH + q);
    vi.x += b0.x + c0.x; vi.y += b0.y + c0.y; vi.z += b0.z + c0.z; vi.w += b0.w + c0.w;
    vf.x += b1.x + c1.x; vf.y += b1.y + c1.y; vf.z += b1.z + c1.z; vf.w += b1.w + c1.w;
    vg.x += b2.x + c2.x; vg.y += b2.y + c2.y; vg.z += b2.z + c2.z; vg.w += b2.w + c2.w;
    vo.x += b3.x + c3.x; vo.y += b3.y + c3.y; vo.z += b3.z + c3.z; vo.w += b3.w + c3.w;
    if (!first) {
        const float* hh = Hh + (size_t)dir * NN * H4 + (size_t)n * H4;
        float4 h0 = *(const float4*)(hh + q);
        float4 h1 = *(const float4*)(hh + HH + q);
        float4 h2 = *(const float4*)(hh + 2 * HH + q);
        float4 h3 = *(const float4*)(hh + 3 * HH + q);
        vi.x += h0.x; vi.y += h0.y; vi.z += h0.z; vi.w += h0.w;
        vf.x += h1.x; vf.y += h1.y; vf.z += h1.z; vf.w += h1.w;
        vg.x += h2.x; vg.y += h2.y; vg.z += h2.z; vg.w += h2.w;
        vo.x += h3.x; vo.y += h3.y; vo.z += h3.z; vo.w += h3.w;
    }
    size_t sidx = (size_t)dir * NN * HH + (size_t)n * HH + q;
    float4 cprev = first ? make_float4(0.f, 0.f, 0.f, 0.f) : *(const float4*)(cbuf + sidx);
    float4 cnew, hv;
#define GATE_COMP(E) { \
    float I = 1.0f / (1.0f + expf(-vi.E)); \
    float Fv = 1.0f / (1.0f + expf(-vf.E)); \
    float G = tanhf(vg.E); \
    float O = 1.0f / (1.0f + expf(-vo.E)); \
    float cn = Fv * cprev.E + I * G; \
    cnew.E = cn; hv.E = O * tanhf(cn); }
    GATE_COMP(x) GATE_COMP(y) GATE_COMP(z) GATE_COMP(w)
#undef GATE_COMP
    *(float4*)(cbuf + sidx) = cnew;
    bf16 h0 = __float2bfloat16(hv.x), h1 = __float2bfloat16(hv.y);
    bf16 h2 = __float2bfloat16(hv.z), h3 = __float2bfloat16(hv.w);
    *(__nv_bfloat162*)(g_hb_hi + sidx)     = __halves2bfloat162(h0, h1);
    *(__nv_bfloat162*)(g_hb_hi + sidx + 2) = __halves2bfloat162(h2, h3);
    *(__nv_bfloat162*)(g_hb_lo + sidx)     = __halves2bfloat162(
        __float2bfloat16(hv.x - __bfloat162float(h0)), __float2bfloat16(hv.y - __bfloat162float(h1)));
    *(__nv_bfloat162*)(g_hb_lo + sidx + 2) = __halves2bfloat162(
        __float2bfloat16(hv.z - __bfloat162float(h2)), __float2bfloat16(hv.w - __bfloat162float(h3)));
    float* hout = dir ? hb : hf;
    *(float4*)(hout + ((size_t)n * KK + t) * HH + q) = hv;
}

// ---------------- attention + pooling + classifier + softmax ----------------
__global__ void final_kernel(const float* __restrict__ rw, const float* __restrict__ rb,
                             const float* __restrict__ ow, const float* __restrict__ ob,
                             float* __restrict__ out) {
    int n = blockIdx.x;
    int t = threadIdx.x;
    __shared__ float red[4];
    __shared__ float sattn[KK];
    __shared__ float sp[HH];
    __shared__ float sl[16];

    for (int k = 0; k < KK; k++) {
        float p = g_hfwd[((size_t)n * KK + k) * HH + t] * rw[t]
                + g_hbwd[((size_t)n * KK + k) * HH + t] * rw[HH + t];
        for (int o = 16; o; o >>= 1) p += __shfl_down_sync(0xffffffffu, p, o);
        if ((t & 31) == 0) red[t >> 5] = p;
        __syncthreads();
        if (t == 0) sattn[k] = red[0] + red[1] + red[2] + red[3] + rb[0];
        __syncthreads();
    }
    if (t == 0) {
        float m = sattn[0];
        for (int k = 1; k < KK; k++) m = fmaxf(m, sattn[k]);
        float s = 0.0f;
        for (int k = 0; k < KK; k++) { sattn[k] = expf(sattn[k] - m); s += sattn[k]; }
        float inv = 1.0f / s;
        for (int k = 0; k < KK; k++) sattn[k] *= inv;
    }
    __syncthreads();
    float pooled = 0.0f;
    for (int k = 0; k < KK; k++)
        pooled += sattn[k] * g_gnn[((size_t)n * KK + k) * HH + t];
    sp[t] = pooled;
    __syncthreads();
    int w = t >> 5, lane = t & 31;
    for (int c = w; c < CC; c += 4) {
        float s = sp[lane] * ow[c * HH + lane]
                + sp[lane + 32] * ow[c * HH + lane + 32]
                + sp[lane + 64] * ow[c * HH + lane + 64]
                + sp[lane + 96] * ow[c * HH + lane + 96];
        for (int o = 16; o; o >>= 1) s += __shfl_down_sync(0xffffffffu, s, o);
        if (lane == 0) sl[c] = s + ob[c];
    }
    __syncthreads();
    if (t == 0) {
        float m = sl[0];
        for (int c = 1; c < CC; c++) m = fmaxf(m, sl[c]);
        float s = 0.0f;
        for (int c = 0; c < CC; c++) { sl[c] = expf(sl[c] - m); s += sl[c]; }
        float inv = 1.0f / s;
        for (int c = 0; c < CC; c++) out[(size_t)n * CC + c] = sl[c] * inv;
    }
}

// ---------------- host orchestration ----------------
extern "C" void kernel_launch(void* const* d_in, const int* in_sizes, int n_in,
                              void* d_out, int out_size) {
    const float* feat  = (const float*)d_in[0];
    const float* adj   = (const float*)d_in[1];
    const float* w1    = (const float*)d_in[2];
    const float* b1    = (const float*)d_in[3];
    const float* w2    = (const float*)d_in[4];
    const float* b2    = (const float*)d_in[5];
    const float* wih_f = (const float*)d_in[6];
    const float* whh_f = (const float*)d_in[7];
    const float* bih_f = (const float*)d_in[8];
    const float* bhh_f = (const float*)d_in[9];
    const float* wih_b = (const float*)d_in[10];
    const float* whh_b = (const float*)d_in[11];
    const float* bih_b = (const float*)d_in[12];
    const float* bhh_b = (const float*)d_in[13];
    const float* rw    = (const float*)d_in[14];
    const float* rb    = (const float*)d_in[15];
    const float* ow    = (const float*)d_in[16];
    const float* ob    = (const float*)d_in[17];
    float* out = (float*)d_out;

    float *dT, *dgnn, *dXG, *dHh, *dcbuf, *dhf, *dhb;
    cudaGetSymbolAddress((void**)&dT,    g_T);
    cudaGetSymbolAddress((void**)&dgnn,  g_gnn);
    cudaGetSymbolAddress((void**)&dXG,   g_XG);
    cudaGetSymbolAddress((void**)&dHh,   g_Hh);
    cudaGetSymbolAddress((void**)&dcbuf, g_cbuf);
    cudaGetSymbolAddress((void**)&dhf,   g_hfwd);
    cudaGetSymbolAddress((void**)&dhb,   g_hbwd);

    bf16 *feat_hi, *feat_lo, *w1_hi, *w1_lo, *w2_hi, *w2_lo;
    bf16 *wihf_hi, *wihf_lo, *whhf_hi, *whhf_lo, *wihb_hi, *wihb_lo, *whhb_hi, *whhb_lo;
    bf16 *h1_hi, *h1_lo, *gnn_hi, *gnn_lo, *hb_hi, *hb_lo;
    cudaGetSymbolAddress((void**)&feat_hi, g_feat_hi); cudaGetSymbolAddress((void**)&feat_lo, g_feat_lo);
    cudaGetSymbolAddress((void**)&w1_hi,   g_w1_hi);   cudaGetSymbolAddress((void**)&w1_lo,   g_w1_lo);
    cudaGetSymbolAddress((void**)&w2_hi,   g_w2_hi);   cudaGetSymbolAddress((void**)&w2_lo,   g_w2_lo);
    cudaGetSymbolAddress((void**)&wihf_hi, g_wihf_hi); cudaGetSymbolAddress((void**)&wihf_lo, g_wihf_lo);
    cudaGetSymbolAddress((void**)&whhf_hi, g_whhf_hi); cudaGetSymbolAddress((void**)&whhf_lo, g_whhf_lo);
    cudaGetSymbolAddress((void**)&wihb_hi, g_wihb_hi); cudaGetSymbolAddress((void**)&wihb_lo, g_wihb_lo);
    cudaGetSymbolAddress((void**)&whhb_hi, g_whhb_hi); cudaGetSymbolAddress((void**)&whhb_lo, g_whhb_lo);
    cudaGetSymbolAddress((void**)&h1_hi,   g_h1_hi);   cudaGetSymbolAddress((void**)&h1_lo,   g_h1_lo);
    cudaGetSymbolAddress((void**)&gnn_hi,  g_gnn_hi);  cudaGetSymbolAddress((void**)&gnn_lo,  g_gnn_lo);
    cudaGetSymbolAddress((void**)&hb_hi,   g_hb_hi);   cudaGetSymbolAddress((void**)&hb_lo,   g_hb_lo);

    static cudaStream_t s2 = nullptr;
    static cudaEvent_t evFork = nullptr, evJoin = nullptr;
    if (!s2) {
        cudaStreamCreateWithFlags(&s2, cudaStreamNonBlocking);
        cudaEventCreateWithFlags(&evFork, cudaEventDisableTiming);
        cudaEventCreateWithFlags(&evJoin, cudaEventDisableTiming);
        cudaFuncSetAttribute((const void*)wmma_gemm<0>,
                             cudaFuncAttributeMaxDynamicSharedMemorySize, SMEM_BYTES);
        cudaFuncSetAttribute((const void*)wmma_gemm<1>,
                             cudaFuncAttributeMaxDynamicSharedMemorySize, SMEM_BYTES);
    }

    const long NH = (long)NN * HH;
    const long XGZ = (long)NN * KK * H4;

    // --- fork: extract + pack (independent of main prep) on side stream ---
    cudaEventRecord(evFork, 0);
    cudaStreamWaitEvent(s2, evFork, 0);
    extract_kernel<<<NN, 256, 0, s2>>>(adj);
    pack_kernel<<<dim3(NN / 8, KK), 256, 0, s2>>>();
    cudaEventRecord(evJoin, s2);

    // --- main stream: split + GCN layer-1 GEMM (independent of extract) ---
    split_all<<<(S_FEAT + 6 * S_W) / 256, 256>>>(feat, w1, w2, wih_f, whh_f, wih_b, whh_b);
    wmma_gemm<0><<<dim3(2, NN / 128, KK), 256, SMEM_BYTES>>>(
        feat_hi, feat_lo, 0, w1_hi, w1_lo, nullptr, nullptr, (long)FF * HH, HH, dT, NH, HH);

    // --- join: spmm needs packed lists ---
    cudaStreamWaitEvent(0, evJoin, 0);

    spmm_kernel<<<dim3(NN / 8, KK), 256>>>(dT, b1, nullptr, h1_hi, h1_lo, HH, NH);

    // GCN layer 2
    wmma_gemm<0><<<dim3(2, NN / 128, KK), 256, SMEM_BYTES>>>(
        h1_hi, h1_lo, NN, w2_hi, w2_lo, nullptr, nullptr, (long)HH * HH, HH, dT, NH, HH);
    spmm_kernel<<<dim3(NN / 8, KK), 256>>>(dT, b2, dgnn, gnn_hi, gnn_lo, (long)KK * HH, HH);

    // LSTM input precompute (both directions batched over z)
    wmma_gemm<1><<<dim3(H4 / 64, (NN * KK) / 128, 2), 256, SMEM_BYTES>>>(
        gnn_hi, gnn_lo, 0, wihf_hi, wihf_lo, wihb_hi, wihb_lo, 0, HH, dXG, XGZ, H4);

    // Bidirectional LSTM, 4 steps; fwd+bwd batched per step
    for (int step = 0; step < KK; step++) {
        if (step > 0)
            wmma_gemm<1><<<dim3(H4 / 64, NN / 128, 2), 256, SMEM_BYTES>>>(
                hb_hi, hb_lo, NN, whhf_hi, whhf_lo, whhb_hi, whhb_lo, 0, HH,
                dHh, (long)NN * H4, H4);
        lstm_gate_kernel<<<dim3((NN * 32) / 256, 2), 256>>>(
            dXG, dHh, bih_f, bhh_f, bih_b, bhh_b, dcbuf, dhf, dhb, step);
    }

    // attention + pooling + classifier
    final_kernel<<<NN, 128>>>(rw, rb, ow, ob, out);

    (void)in_sizes; (void)n_in; (void)out_size;
}